// round 1
// baseline (speedup 1.0000x reference)
#include <cuda_runtime.h>
#include <math.h>

// Problem constants
#define B_    16
#define N_    2048
#define D_    128        // model dim == head dim
#define H_    8
#define F_    65         // rfft(128) -> 65 freqs
#define ROWS_ 32768      // B_*N_
#define N1_   3120       // 3 regions (q,k,v) * H_ * 130 (65 re + 65 im)
#define NZ_   1040       // H_ * 130
#define SCALE_ (1.0f/65.0f)

// ---------------- scratch (static device, no allocation) ----------------
__device__ float g_W1[D_ * N1_];               // folded qkv weights (x -> freq features)
__device__ float g_Mout[NZ_ * D_];             // folded irfft + w_out
__device__ float g_F[(size_t)ROWS_ * N1_];     // raw freq features (re/im for q,k,v)
__device__ float g_aq[(size_t)ROWS_ * H_ * F_];// |q_ft|
__device__ float g_ak[(size_t)ROWS_ * H_ * F_];// |k_ft|
__device__ float g_att[B_ * H_ * F_ * F_];     // softmax(att)
__device__ float g_Z[(size_t)ROWS_ * NZ_];     // att-applied v (re/im per head)

// ---------------- weight folding ----------------
// W1[d][c]: column layout: region(q=0,k=1,v=2)*1040 + h*130 + (f | 65+f)
// re coeff: cos(2*pi*f*dd/128); im coeff: -sin(...); q,k scaled by SCALE_
__global__ void build_w1_kernel(const float* __restrict__ w_qkv) {
    __shared__ float cs[128], sn[128];
    int t = threadIdx.x;
    if (t < 128) {
        float ang = (float)t / 64.0f;   // 2*pi*t/128 = pi * t/64
        cs[t] = cospif(ang);
        sn[t] = sinpif(ang);
    }
    __syncthreads();
    const int total = D_ * N1_;
    for (int idx = blockIdx.x * blockDim.x + t; idx < total; idx += gridDim.x * blockDim.x) {
        int d = idx / N1_;
        int c = idx - d * N1_;
        int region = c / 1040;
        int cc = c - region * 1040;
        int h = cc / 130;
        int u = cc - h * 130;
        int f = (u < 65) ? u : (u - 65);
        const float* w = w_qkv + (size_t)d * 3072 + region * 1024 + h * 128;
        float acc = 0.f;
        if (u < 65) {
            #pragma unroll 8
            for (int dd = 0; dd < 128; dd++) acc += w[dd] * cs[(f * dd) & 127];
        } else {
            #pragma unroll 8
            for (int dd = 0; dd < 128; dd++) acc -= w[dd] * sn[(f * dd) & 127];
        }
        g_W1[idx] = (region == 2) ? acc : acc * SCALE_;
    }
}

// Mout[r][o]: r = h*130 + (f for Re | 65+f for Im)
// irfft: x_t = (1/128)[Re z0 + 2*sum_{f=1..63}(Re z_f cos - Im z_f sin) + Re z64*(-1)^t]
// (imag parts of bins 0 and 64 are ignored by irfft -> zero rows)
__global__ void build_mout_kernel(const float* __restrict__ w_out) {
    __shared__ float cs[128], sn[128];
    int t = threadIdx.x;
    if (t < 128) {
        float ang = (float)t / 64.0f;
        cs[t] = cospif(ang);
        sn[t] = sinpif(ang);
    }
    __syncthreads();
    const int total = NZ_ * D_;
    for (int idx = blockIdx.x * blockDim.x + t; idx < total; idx += gridDim.x * blockDim.x) {
        int r = idx / D_;
        int o = idx - r * D_;
        int h = r / 130;
        int u = r - h * 130;
        int is_im = (u >= 65);
        int f = is_im ? (u - 65) : u;
        float acc = 0.f;
        if (!is_im) {
            #pragma unroll 8
            for (int t2 = 0; t2 < 128; t2++)
                acc += cs[(f * t2) & 127] * w_out[(size_t)(h * 128 + t2) * 128 + o];
            acc *= ((f == 0 || f == 64) ? 1.0f : 2.0f) / 128.0f;
        } else if (f != 0 && f != 64) {
            #pragma unroll 8
            for (int t2 = 0; t2 < 128; t2++)
                acc -= sn[(f * t2) & 127] * w_out[(size_t)(h * 128 + t2) * 128 + o];
            acc *= 2.0f / 128.0f;
        }
        g_Mout[idx] = acc;
    }
}

// ---------------- generic 128x128x16 SGEMM, 8x8 register tile ----------------
__device__ __forceinline__ void sgemm_body(
    const float* __restrict__ A, const float* __restrict__ Bm,
    float* __restrict__ C, int Ncols, int K, const float* __restrict__ bias)
{
    __shared__ float As[16][128];
    __shared__ float Bs[16][128];
    const int tid = threadIdx.x;
    const int bm = blockIdx.y * 128;
    const int bn = blockIdx.x * 128;
    const int am = tid >> 1;
    const int akk = (tid & 1) * 8;
    const int tm = (tid >> 4) * 8;
    const int tn = (tid & 15) * 8;
    float acc[8][8];
    #pragma unroll
    for (int i = 0; i < 8; i++)
        #pragma unroll
        for (int j = 0; j < 8; j++) acc[i][j] = 0.f;

    const bool fullN = (bn + 128 <= Ncols);
    for (int k0 = 0; k0 < K; k0 += 16) {
        float4 a0 = *(const float4*)(A + (size_t)(bm + am) * K + k0 + akk);
        float4 a1 = *(const float4*)(A + (size_t)(bm + am) * K + k0 + akk + 4);
        As[akk + 0][am] = a0.x; As[akk + 1][am] = a0.y;
        As[akk + 2][am] = a0.z; As[akk + 3][am] = a0.w;
        As[akk + 4][am] = a1.x; As[akk + 5][am] = a1.y;
        As[akk + 6][am] = a1.z; As[akk + 7][am] = a1.w;
        if (fullN) {
            #pragma unroll
            for (int i = 0; i < 2; i++) {
                int li = tid * 2 + i;
                int kk = li >> 5;
                int nn = (li & 31) * 4;
                *(float4*)(&Bs[kk][nn]) =
                    *(const float4*)(Bm + (size_t)(k0 + kk) * Ncols + bn + nn);
            }
        } else {
            #pragma unroll
            for (int i = 0; i < 2; i++) {
                int li = tid * 2 + i;
                int kk = li >> 5;
                int nn = (li & 31) * 4;
                #pragma unroll
                for (int j = 0; j < 4; j++) {
                    int col = bn + nn + j;
                    Bs[kk][nn + j] = (col < Ncols)
                        ? Bm[(size_t)(k0 + kk) * Ncols + col] : 0.f;
                }
            }
        }
        __syncthreads();
        #pragma unroll
        for (int kk = 0; kk < 16; kk++) {
            float a[8], b[8];
            #pragma unroll
            for (int i = 0; i < 8; i++) a[i] = As[kk][tm + i];
            #pragma unroll
            for (int j = 0; j < 8; j++) b[j] = Bs[kk][tn + j];
            #pragma unroll
            for (int i = 0; i < 8; i++)
                #pragma unroll
                for (int j = 0; j < 8; j++) acc[i][j] += a[i] * b[j];
        }
        __syncthreads();
    }
    #pragma unroll
    for (int i = 0; i < 8; i++) {
        int row = bm + tm + i;
        #pragma unroll
        for (int j = 0; j < 8; j++) {
            int col = bn + tn + j;
            if (col < Ncols) {
                float v = acc[i][j];
                if (bias) v += bias[col];
                C[(size_t)row * Ncols + col] = v;
            }
        }
    }
}

__global__ void __launch_bounds__(256) gemm1_kernel(const float* __restrict__ X) {
    sgemm_body(X, g_W1, g_F, N1_, D_, nullptr);
}
__global__ void __launch_bounds__(256) gemm2_kernel(float* __restrict__ out,
                                                    const float* __restrict__ bias) {
    sgemm_body(g_Z, g_Mout, out, D_, NZ_, bias);
}

// ---------------- |q_ft|, |k_ft| ----------------
__global__ void absqk_kernel() {
    const int total = ROWS_ * H_ * F_;
    for (int idx = blockIdx.x * blockDim.x + threadIdx.x; idx < total;
         idx += gridDim.x * blockDim.x) {
        int f = idx % F_;
        int t = idx / F_;
        int h = t & 7;
        int row = t >> 3;
        const float* Fr = g_F + (size_t)row * N1_;
        int c = h * 130 + f;
        float qre = Fr[c], qim = Fr[c + 65];
        g_aq[idx] = sqrtf(qre * qre + qim * qim);
        float kre = Fr[1040 + c], kim = Fr[1040 + c + 65];
        g_ak[idx] = sqrtf(kre * kre + kim * kim);
    }
}

// ---------------- att = aq^T @ ak (over e=2048) + softmax over y ----------------
__global__ void __launch_bounds__(256) att_kernel() {
    __shared__ float sm[8320];            // chunk buffers, then reused for att tile
    float* aqs = sm;                      // [64][65]
    float* aks = sm + 4160;               // [64][65]
    int bh = blockIdx.x;
    int b = bh >> 3, h = bh & 7;
    int tid = threadIdx.x;
    int tx = tid & 15, ty = tid >> 4;
    int xs[5], ys[5];
    #pragma unroll
    for (int i = 0; i < 5; i++) {
        int x = tx + 16 * i; xs[i] = (x < 65) ? x : 0;
        int y = ty + 16 * i; ys[i] = (y < 65) ? y : 0;
    }
    float acc[5][5];
    #pragma unroll
    for (int i = 0; i < 5; i++)
        #pragma unroll
        for (int j = 0; j < 5; j++) acc[i][j] = 0.f;

    for (int e0 = 0; e0 < 2048; e0 += 64) {
        for (int idx = tid; idx < 4160; idx += 256) {
            int r = idx / 65, f = idx - r * 65;
            size_t g = ((size_t)((b * 2048 + e0 + r) * 8 + h)) * 65 + f;
            aqs[idx] = g_aq[g];
            aks[idx] = g_ak[g];
        }
        __syncthreads();
        #pragma unroll 4
        for (int e = 0; e < 64; e++) {
            float av[5], bv[5];
            #pragma unroll
            for (int i = 0; i < 5; i++) av[i] = aqs[e * 65 + xs[i]];
            #pragma unroll
            for (int j = 0; j < 5; j++) bv[j] = aks[e * 65 + ys[j]];
            #pragma unroll
            for (int i = 0; i < 5; i++)
                #pragma unroll
                for (int j = 0; j < 5; j++) acc[i][j] += av[i] * bv[j];
        }
        __syncthreads();
    }
    // stage att tile into smem (reuse sm)
    #pragma unroll
    for (int i = 0; i < 5; i++) {
        int x = tx + 16 * i;
        if (x < 65)
            #pragma unroll
            for (int j = 0; j < 5; j++) {
                int y = ty + 16 * j;
                if (y < 65) sm[x * 65 + y] = acc[i][j];
            }
    }
    __syncthreads();
    // softmax rows (x) over y, 8 warps
    int warp = tid >> 5, lane = tid & 31;
    for (int x = warp; x < 65; x += 8) {
        float m = -3.4e38f;
        for (int y = lane; y < 65; y += 32) m = fmaxf(m, sm[x * 65 + y]);
        #pragma unroll
        for (int o = 16; o; o >>= 1) m = fmaxf(m, __shfl_xor_sync(0xffffffffu, m, o));
        float s = 0.f;
        for (int y = lane; y < 65; y += 32) {
            float v = expf(sm[x * 65 + y] - m);
            sm[x * 65 + y] = v;
            s += v;
        }
        #pragma unroll
        for (int o = 16; o; o >>= 1) s += __shfl_xor_sync(0xffffffffu, s, o);
        float inv = 1.0f / s;
        for (int y = lane; y < 65; y += 32)
            g_att[(size_t)bh * 4225 + x * 65 + y] = sm[x * 65 + y] * inv;
    }
}

// ---------------- z[e,x] = sum_y att[x,y] * v_{re,im}[e,y] ----------------
__global__ void __launch_bounds__(256) apply_kernel() {
    __shared__ float att_s[4225];
    __shared__ float vs[4160];            // [64][65]
    int bh = blockIdx.y;
    int b = bh >> 3, h = bh & 7;
    int e0 = blockIdx.x * 64;
    int tid = threadIdx.x;
    int tx = tid & 15, ty = tid >> 4;
    for (int idx = tid; idx < 4225; idx += 256)
        att_s[idx] = g_att[(size_t)bh * 4225 + idx];
    int xs[5];
    #pragma unroll
    for (int j = 0; j < 5; j++) { int x = tx + 16 * j; xs[j] = (x < 65) ? x : 0; }

    for (int ri = 0; ri < 2; ri++) {
        __syncthreads();                  // att_s ready / vs safe to overwrite
        for (int idx = tid; idx < 4160; idx += 256) {
            int r = idx / 65, y = idx - r * 65;
            vs[idx] = g_F[(size_t)(b * 2048 + e0 + r) * N1_ + 2080 + h * 130 + ri * 65 + y];
        }
        __syncthreads();
        float acc[4][5];
        #pragma unroll
        for (int i = 0; i < 4; i++)
            #pragma unroll
            for (int j = 0; j < 5; j++) acc[i][j] = 0.f;
        #pragma unroll 5
        for (int y = 0; y < 65; y++) {
            float av[4], bv[5];
            #pragma unroll
            for (int i = 0; i < 4; i++) av[i] = vs[(ty + 16 * i) * 65 + y];
            #pragma unroll
            for (int j = 0; j < 5; j++) bv[j] = att_s[xs[j] * 65 + y];
            #pragma unroll
            for (int i = 0; i < 4; i++)
                #pragma unroll
                for (int j = 0; j < 5; j++) acc[i][j] += av[i] * bv[j];
        }
        #pragma unroll
        for (int i = 0; i < 4; i++) {
            int row = b * 2048 + e0 + ty + 16 * i;
            #pragma unroll
            for (int j = 0; j < 5; j++) {
                int x = tx + 16 * j;
                if (x < 65)
                    g_Z[(size_t)row * NZ_ + h * 130 + ri * 65 + x] = acc[i][j];
            }
        }
    }
}

// ---------------- launch ----------------
extern "C" void kernel_launch(void* const* d_in, const int* in_sizes, int n_in,
                              void* d_out, int out_size) {
    const float* x      = (const float*)d_in[0];  // [16,2048,128]
    const float* w_qkv  = (const float*)d_in[1];  // [128,3072]
    const float* w_out  = (const float*)d_in[2];  // [1024,128]
    const float* b_out  = (const float*)d_in[3];  // [128]
    float* out = (float*)d_out;                   // [16,2048,128]

    build_w1_kernel<<<480, 256>>>(w_qkv);
    build_mout_kernel<<<256, 256>>>(w_out);
    gemm1_kernel<<<dim3((N1_ + 127) / 128, ROWS_ / 128), 256>>>(x);
    absqk_kernel<<<2048, 256>>>();
    att_kernel<<<B_ * H_, 256>>>();
    apply_kernel<<<dim3(N_ / 64, B_ * H_), 256>>>();
    gemm2_kernel<<<dim3(1, ROWS_ / 128), 256>>>(out, b_out);
}

// round 3
// speedup vs baseline: 1.1534x; 1.1534x over previous
#include <cuda_runtime.h>
#include <cuda_bf16.h>
#include <cstdint>
#include <math.h>

// Problem constants
#define B_    16
#define N_    2048
#define D_    128
#define H_    8
#define F_    65
#define ROWS_ 32768
#define N1_   3120       // q,k,v * 8 heads * 130 (65 re + 65 im)
#define N1P_  3200       // padded to 25*128
#define NZ_   1040       // 8 * 130
#define NZP_  1152       // padded to 9*128
#define SCALE_ (1.0f/65.0f)

// ---------------- scratch (static device, no allocation) ----------------
__device__ __nv_bfloat16 g_W1T_hi[N1P_ * D_];   // [3200][128] B for gemm1 (n-major, k contig)
__device__ __nv_bfloat16 g_W1T_lo[N1P_ * D_];
__device__ __nv_bfloat16 g_MoutT_hi[D_ * NZP_]; // [128][1152] B for gemm2
__device__ __nv_bfloat16 g_MoutT_lo[D_ * NZP_];
__device__ float g_F[(size_t)ROWS_ * N1_];      // freq features fp32
__device__ float g_aq[(size_t)ROWS_ * H_ * F_];
__device__ float g_ak[(size_t)ROWS_ * H_ * F_];
__device__ float g_att[B_ * H_ * F_ * F_];
__device__ __nv_bfloat16 g_Zhi[(size_t)ROWS_ * NZP_]; // pads stay 0 (static init)
__device__ __nv_bfloat16 g_Zlo[(size_t)ROWS_ * NZP_];

// ---------------- helpers ----------------
__device__ __forceinline__ uint32_t smem_u32(const void* p) {
    uint32_t a;
    asm("{ .reg .u64 t; cvta.to.shared.u64 t, %1; cvt.u32.u64 %0, t; }" : "=r"(a) : "l"(p));
    return a;
}
__device__ __forceinline__ void ldsm_x4(uint32_t* r, uint32_t addr) {
    asm volatile("ldmatrix.sync.aligned.m8n8.x4.shared.b16 {%0,%1,%2,%3}, [%4];"
                 : "=r"(r[0]), "=r"(r[1]), "=r"(r[2]), "=r"(r[3]) : "r"(addr));
}
__device__ __forceinline__ void mma16816(float* c, const uint32_t* a, const uint32_t* b) {
    asm volatile("mma.sync.aligned.m16n8k16.row.col.f32.bf16.bf16.f32 "
                 "{%0,%1,%2,%3}, {%4,%5,%6,%7}, {%8,%9}, {%0,%1,%2,%3};"
                 : "+f"(c[0]), "+f"(c[1]), "+f"(c[2]), "+f"(c[3])
                 : "r"(a[0]), "r"(a[1]), "r"(a[2]), "r"(a[3]), "r"(b[0]), "r"(b[1]));
}
__device__ __forceinline__ uint32_t pack_bf(__nv_bfloat16 a, __nv_bfloat16 b) {
    __nv_bfloat162 p = __halves2bfloat162(a, b);
    return *reinterpret_cast<uint32_t*>(&p);
}
// swizzled offset within a [rows][128 bf16] tile (row = 256 bytes)
__device__ __forceinline__ uint32_t swz(int row, int colbyte) {
    return (uint32_t)(row * 256 + (colbyte ^ ((row & 7) << 4)));
}

// SMEM layout for both TC GEMMs: 4 tiles of 128x128 bf16 (32 KB each)
#define SM_AHI  0
#define SM_ALO  32768
#define SM_BHI  65536
#define SM_BLO  98304
#define SM_TOT  131072

// one 3-pass (hi*hi + hi*lo + lo*hi) mma sweep over a resident 128x128 K-chunk
__device__ __forceinline__ void mma_chunk(uint32_t sb, int lane, int wm, int wn,
                                          float c[2][8][4]) {
    const uint32_t aoff[3] = {SM_AHI, SM_AHI, SM_ALO};
    const uint32_t boff[3] = {SM_BHI, SM_BLO, SM_BHI};
    #pragma unroll
    for (int p = 0; p < 3; p++) {
        uint32_t sA = sb + aoff[p], sB = sb + boff[p];
        #pragma unroll
        for (int ks = 0; ks < 8; ks++) {
            int colb = ks * 32 + (lane >> 4) * 16;   // byte col of this lane's 8x8 row
            uint32_t a[2][4];
            #pragma unroll
            for (int tm = 0; tm < 2; tm++) {
                int r = wm * 32 + tm * 16 + (lane & 15);
                ldsm_x4(a[tm], sA + swz(r, colb));
            }
            uint32_t b[8][2];
            #pragma unroll
            for (int ng = 0; ng < 4; ng++) {
                int n = wn * 64 + ng * 16 + (lane & 15);
                uint32_t q[4];
                ldsm_x4(q, sB + swz(n, colb));
                b[2 * ng][0] = q[0]; b[2 * ng + 1][0] = q[1];
                b[2 * ng][1] = q[2]; b[2 * ng + 1][1] = q[3];
            }
            #pragma unroll
            for (int tm = 0; tm < 2; tm++)
                #pragma unroll
                for (int tn = 0; tn < 8; tn++)
                    mma16816(c[tm][tn], a[tm], b[tn]);
        }
    }
}

// ---------------- weight folding ----------------
__global__ void build_w1_kernel(const float* __restrict__ w_qkv) {
    __shared__ float cs[128], sn[128];
    int t = threadIdx.x;
    if (t < 128) {
        float ang = (float)t / 64.0f;
        cs[t] = cospif(ang);
        sn[t] = sinpif(ang);
    }
    __syncthreads();
    const int total = N1P_ * D_;
    for (int idx = blockIdx.x * blockDim.x + t; idx < total; idx += gridDim.x * blockDim.x) {
        int c = idx >> 7, d = idx & 127;
        float acc = 0.f;
        if (c < N1_) {
            int region = c / 1040;
            int cc = c - region * 1040;
            int hd = cc / 130;
            int u = cc - hd * 130;
            int f = (u < 65) ? u : (u - 65);
            const float* w = w_qkv + (size_t)d * 3072 + region * 1024 + hd * 128;
            if (u < 65) {
                #pragma unroll 8
                for (int dd = 0; dd < 128; dd++) acc += w[dd] * cs[(f * dd) & 127];
            } else {
                #pragma unroll 8
                for (int dd = 0; dd < 128; dd++) acc -= w[dd] * sn[(f * dd) & 127];
            }
            if (region != 2) acc *= SCALE_;
        }
        __nv_bfloat16 hi = __float2bfloat16(acc);
        __nv_bfloat16 lo = __float2bfloat16(acc - __bfloat162float(hi));
        g_W1T_hi[idx] = hi;
        g_W1T_lo[idx] = lo;
    }
}

__global__ void build_mout_kernel(const float* __restrict__ w_out) {
    __shared__ float cs[128], sn[128];
    int t = threadIdx.x;
    if (t < 128) {
        float ang = (float)t / 64.0f;
        cs[t] = cospif(ang);
        sn[t] = sinpif(ang);
    }
    __syncthreads();
    const int total = D_ * NZP_;
    for (int idx = blockIdx.x * blockDim.x + t; idx < total; idx += gridDim.x * blockDim.x) {
        int o = idx / NZP_, r = idx - o * NZP_;
        float acc = 0.f;
        if (r < NZ_) {
            int hd = r / 130;
            int u = r - hd * 130;
            int is_im = (u >= 65);
            int f = is_im ? (u - 65) : u;
            if (!is_im) {
                #pragma unroll 8
                for (int t2 = 0; t2 < 128; t2++)
                    acc += cs[(f * t2) & 127] * w_out[(size_t)(hd * 128 + t2) * 128 + o];
                acc *= ((f == 0 || f == 64) ? 1.0f : 2.0f) / 128.0f;
            } else if (f != 0 && f != 64) {
                #pragma unroll 8
                for (int t2 = 0; t2 < 128; t2++)
                    acc -= sn[(f * t2) & 127] * w_out[(size_t)(hd * 128 + t2) * 128 + o];
                acc *= 2.0f / 128.0f;
            }
        }
        __nv_bfloat16 hi = __float2bfloat16(acc);
        __nv_bfloat16 lo = __float2bfloat16(acc - __bfloat162float(hi));
        g_MoutT_hi[idx] = hi;
        g_MoutT_lo[idx] = lo;
    }
}

// ---------------- GEMM1: g_F = X[32768,128] @ W1 (mma.sync bf16 split) ----------------
__global__ void __launch_bounds__(256, 1) gemm1_tc(const float* __restrict__ X) {
    extern __shared__ char smem[];
    uint32_t sb = smem_u32(smem);
    int tid = threadIdx.x;
    int lane = tid & 31, wid = tid >> 5;
    int wm = wid & 3, wn = wid >> 2;
    int bm = blockIdx.y * 128, bn = blockIdx.x * 128;

    // stage A: X fp32 -> bf16 hi/lo, swizzled
    for (int u = tid; u < 4096; u += 256) {
        int r = u >> 5, c4 = (u & 31) * 4;
        float4 v = *(const float4*)(X + (size_t)(bm + r) * 128 + c4);
        __nv_bfloat16 h0 = __float2bfloat16(v.x), h1 = __float2bfloat16(v.y);
        __nv_bfloat16 h2 = __float2bfloat16(v.z), h3 = __float2bfloat16(v.w);
        uint32_t ad = swz(r, c4 * 2);
        *(uint2*)(smem + SM_AHI + ad) = make_uint2(pack_bf(h0, h1), pack_bf(h2, h3));
        *(uint2*)(smem + SM_ALO + ad) = make_uint2(
            pack_bf(__float2bfloat16(v.x - __bfloat162float(h0)),
                    __float2bfloat16(v.y - __bfloat162float(h1))),
            pack_bf(__float2bfloat16(v.z - __bfloat162float(h2)),
                    __float2bfloat16(v.w - __bfloat162float(h3))));
    }
    // stage B: W1T hi/lo, swizzled
    for (int u = tid; u < 2048; u += 256) {
        int r = u >> 4, c8 = (u & 15) * 8;
        uint32_t ad = swz(r, c8 * 2);
        *(uint4*)(smem + SM_BHI + ad) = *(const uint4*)(g_W1T_hi + (size_t)(bn + r) * 128 + c8);
        *(uint4*)(smem + SM_BLO + ad) = *(const uint4*)(g_W1T_lo + (size_t)(bn + r) * 128 + c8);
    }
    __syncthreads();

    float c[2][8][4];
    #pragma unroll
    for (int i = 0; i < 2; i++)
        #pragma unroll
        for (int j = 0; j < 8; j++)
            #pragma unroll
            for (int k = 0; k < 4; k++) c[i][j][k] = 0.f;

    mma_chunk(sb, lane, wm, wn, c);

    // epilogue: fp32 to g_F with N1_ guard (pair-granular; N1_ even)
    int g = lane >> 2, cp = (lane & 3) * 2;
    #pragma unroll
    for (int tm = 0; tm < 2; tm++)
        #pragma unroll
        for (int hf = 0; hf < 2; hf++) {
            size_t row = (size_t)bm + wm * 32 + tm * 16 + hf * 8 + g;
            float* dst = g_F + row * N1_;
            #pragma unroll
            for (int tn = 0; tn < 8; tn++) {
                int col = bn + wn * 64 + tn * 8 + cp;
                if (col < N1_) {
                    float2 v = make_float2(c[tm][tn][hf * 2], c[tm][tn][hf * 2 + 1]);
                    *(float2*)(dst + col) = v;
                }
            }
        }
}

// ---------------- GEMM2: out = Z[32768,1152] @ MoutT^T + bias ----------------
__global__ void __launch_bounds__(256, 1) gemm2_tc(float* __restrict__ out,
                                                   const float* __restrict__ bias) {
    extern __shared__ char smem[];
    uint32_t sb = smem_u32(smem);
    int tid = threadIdx.x;
    int lane = tid & 31, wid = tid >> 5;
    int wm = wid & 3, wn = wid >> 2;
    int bm = blockIdx.y * 128;

    float c[2][8][4];
    #pragma unroll
    for (int i = 0; i < 2; i++)
        #pragma unroll
        for (int j = 0; j < 8; j++)
            #pragma unroll
            for (int k = 0; k < 4; k++) c[i][j][k] = 0.f;

    for (int kc = 0; kc < 9; kc++) {
        int k0 = kc * 128;
        __syncthreads();
        for (int u = tid; u < 2048; u += 256) {
            int r = u >> 4, c8 = (u & 15) * 8;
            uint32_t ad = swz(r, c8 * 2);
            *(uint4*)(smem + SM_AHI + ad) = *(const uint4*)(g_Zhi + (size_t)(bm + r) * NZP_ + k0 + c8);
            *(uint4*)(smem + SM_ALO + ad) = *(const uint4*)(g_Zlo + (size_t)(bm + r) * NZP_ + k0 + c8);
            *(uint4*)(smem + SM_BHI + ad) = *(const uint4*)(g_MoutT_hi + (size_t)r * NZP_ + k0 + c8);
            *(uint4*)(smem + SM_BLO + ad) = *(const uint4*)(g_MoutT_lo + (size_t)r * NZP_ + k0 + c8);
        }
        __syncthreads();
        mma_chunk(sb, lane, wm, wn, c);
    }

    int g = lane >> 2, cp = (lane & 3) * 2;
    #pragma unroll
    for (int tm = 0; tm < 2; tm++)
        #pragma unroll
        for (int hf = 0; hf < 2; hf++) {
            size_t row = (size_t)bm + wm * 32 + tm * 16 + hf * 8 + g;
            float* dst = out + row * 128;
            #pragma unroll
            for (int tn = 0; tn < 8; tn++) {
                int col = wn * 64 + tn * 8 + cp;
                float2 bv = *(const float2*)(bias + col);
                float2 v = make_float2(c[tm][tn][hf * 2] + bv.x,
                                       c[tm][tn][hf * 2 + 1] + bv.y);
                *(float2*)(dst + col) = v;
            }
        }
}

// ---------------- |q_ft|, |k_ft| ----------------
__global__ void absqk_kernel() {
    const int total = ROWS_ * H_ * F_;
    for (int idx = blockIdx.x * blockDim.x + threadIdx.x; idx < total;
         idx += gridDim.x * blockDim.x) {
        int f = idx % F_;
        int t = idx / F_;
        int h = t & 7;
        int row = t >> 3;
        const float* Fr = g_F + (size_t)row * N1_;
        int c = h * 130 + f;
        float qre = Fr[c], qim = Fr[c + 65];
        g_aq[idx] = sqrtf(qre * qre + qim * qim);
        float kre = Fr[1040 + c], kim = Fr[1040 + c + 65];
        g_ak[idx] = sqrtf(kre * kre + kim * kim);
    }
}

// ---------------- att = aq^T @ ak + softmax ----------------
__global__ void __launch_bounds__(256) att_kernel() {
    __shared__ float sm[8320];
    float* aqs = sm;
    float* aks = sm + 4160;
    int bh = blockIdx.x;
    int b = bh >> 3, h = bh & 7;
    int tid = threadIdx.x;
    int tx = tid & 15, ty = tid >> 4;
    int xs[5], ys[5];
    #pragma unroll
    for (int i = 0; i < 5; i++) {
        int x = tx + 16 * i; xs[i] = (x < 65) ? x : 0;
        int y = ty + 16 * i; ys[i] = (y < 65) ? y : 0;
    }
    float acc[5][5];
    #pragma unroll
    for (int i = 0; i < 5; i++)
        #pragma unroll
        for (int j = 0; j < 5; j++) acc[i][j] = 0.f;

    for (int e0 = 0; e0 < 2048; e0 += 64) {
        for (int idx = tid; idx < 4160; idx += 256) {
            int r = idx / 65, f = idx - r * 65;
            size_t gidx = ((size_t)((b * 2048 + e0 + r) * 8 + h)) * 65 + f;
            aqs[idx] = g_aq[gidx];
            aks[idx] = g_ak[gidx];
        }
        __syncthreads();
        #pragma unroll 4
        for (int e = 0; e < 64; e++) {
            float av[5], bv[5];
            #pragma unroll
            for (int i = 0; i < 5; i++) av[i] = aqs[e * 65 + xs[i]];
            #pragma unroll
            for (int j = 0; j < 5; j++) bv[j] = aks[e * 65 + ys[j]];
            #pragma unroll
            for (int i = 0; i < 5; i++)
                #pragma unroll
                for (int j = 0; j < 5; j++) acc[i][j] += av[i] * bv[j];
        }
        __syncthreads();
    }
    #pragma unroll
    for (int i = 0; i < 5; i++) {
        int x = tx + 16 * i;
        if (x < 65)
            #pragma unroll
            for (int j = 0; j < 5; j++) {
                int y = ty + 16 * j;
                if (y < 65) sm[x * 65 + y] = acc[i][j];
            }
    }
    __syncthreads();
    int warp = tid >> 5, lane = tid & 31;
    for (int x = warp; x < 65; x += 8) {
        float m = -3.4e38f;
        for (int y = lane; y < 65; y += 32) m = fmaxf(m, sm[x * 65 + y]);
        #pragma unroll
        for (int o = 16; o; o >>= 1) m = fmaxf(m, __shfl_xor_sync(0xffffffffu, m, o));
        float s = 0.f;
        for (int y = lane; y < 65; y += 32) {
            float v = expf(sm[x * 65 + y] - m);
            sm[x * 65 + y] = v;
            s += v;
        }
        #pragma unroll
        for (int o = 16; o; o >>= 1) s += __shfl_xor_sync(0xffffffffu, s, o);
        float inv = 1.0f / s;
        for (int y = lane; y < 65; y += 32)
            g_att[(size_t)bh * 4225 + x * 65 + y] = sm[x * 65 + y] * inv;
    }
}

// ---------------- z[e,x] = sum_y att[x,y] * v[e,y] -> bf16 hi/lo ----------------
__global__ void __launch_bounds__(256) apply_kernel() {
    __shared__ float att_s[4225];
    __shared__ float vs[4160];
    int bh = blockIdx.y;
    int b = bh >> 3, hd = bh & 7;
    int e0 = blockIdx.x * 64;
    int tid = threadIdx.x;
    int tx = tid & 15, ty = tid >> 4;
    for (int idx = tid; idx < 4225; idx += 256)
        att_s[idx] = g_att[(size_t)bh * 4225 + idx];
    int xs[5];
    #pragma unroll
    for (int j = 0; j < 5; j++) { int x = tx + 16 * j; xs[j] = (x < 65) ? x : 0; }

    for (int ri = 0; ri < 2; ri++) {
        __syncthreads();
        for (int idx = tid; idx < 4160; idx += 256) {
            int r = idx / 65, y = idx - r * 65;
            vs[idx] = g_F[(size_t)(b * 2048 + e0 + r) * N1_ + 2080 + hd * 130 + ri * 65 + y];
        }
        __syncthreads();
        float acc[4][5];
        #pragma unroll
        for (int i = 0; i < 4; i++)
            #pragma unroll
            for (int j = 0; j < 5; j++) acc[i][j] = 0.f;
        #pragma unroll 5
        for (int y = 0; y < 65; y++) {
            float av[4], bv[5];
            #pragma unroll
            for (int i = 0; i < 4; i++) av[i] = vs[(ty + 16 * i) * 65 + y];
            #pragma unroll
            for (int j = 0; j < 5; j++) bv[j] = att_s[xs[j] * 65 + y];
            #pragma unroll
            for (int i = 0; i < 4; i++)
                #pragma unroll
                for (int j = 0; j < 5; j++) acc[i][j] += av[i] * bv[j];
        }
        #pragma unroll
        for (int i = 0; i < 4; i++) {
            size_t row = (size_t)b * 2048 + e0 + ty + 16 * i;
            #pragma unroll
            for (int j = 0; j < 5; j++) {
                int x = tx + 16 * j;
                if (x < 65) {
                    float v = acc[i][j];
                    __nv_bfloat16 hi = __float2bfloat16(v);
                    __nv_bfloat16 lo = __float2bfloat16(v - __bfloat162float(hi));
                    size_t off = row * NZP_ + hd * 130 + ri * 65 + x;
                    g_Zhi[off] = hi;
                    g_Zlo[off] = lo;
                }
            }
        }
    }
}

// ---------------- launch ----------------
extern "C" void kernel_launch(void* const* d_in, const int* in_sizes, int n_in,
                              void* d_out, int out_size) {
    const float* x     = (const float*)d_in[0];
    const float* w_qkv = (const float*)d_in[1];
    const float* w_out = (const float*)d_in[2];
    const float* b_out = (const float*)d_in[3];
    float* out = (float*)d_out;

    cudaFuncSetAttribute(gemm1_tc, cudaFuncAttributeMaxDynamicSharedMemorySize, SM_TOT);
    cudaFuncSetAttribute(gemm2_tc, cudaFuncAttributeMaxDynamicSharedMemorySize, SM_TOT);

    build_w1_kernel<<<480, 256>>>(w_qkv);
    build_mout_kernel<<<288, 256>>>(w_out);
    gemm1_tc<<<dim3(N1P_ / 128, ROWS_ / 128), 256, SM_TOT>>>(x);
    absqk_kernel<<<2048, 256>>>();
    att_kernel<<<B_ * H_, 256>>>();
    apply_kernel<<<dim3(N_ / 64, B_ * H_), 256>>>();
    gemm2_tc<<<dim3(1, ROWS_ / 128), 256, SM_TOT>>>(out, b_out);
}

// round 4
// speedup vs baseline: 1.3317x; 1.1546x over previous
#include <cuda_runtime.h>
#include <cuda_bf16.h>
#include <cstdint>
#include <math.h>

// Problem constants
#define B_    16
#define N_    2048
#define D_    128
#define H_    8
#define F_    65
#define ROWS_ 32768
#define N1_   3120       // q,k,v * 8 heads * 130 (re/im interleaved: u = 2f+p)
#define N1P_  3200       // padded to 25*128
#define NK_   1040       // 8 * 130 (V feature dim = gemm2 K)
#define NKP_  1152       // padded to 9*128
#define SCALE_ (1.0f/65.0f)

// ---------------- scratch (static device, no allocation) ----------------
__device__ __nv_bfloat16 g_W1T_hi[N1P_ * D_];    // [3200][128] gemm1 B (n-major, k contig)
__device__ __nv_bfloat16 g_W1T_lo[N1P_ * D_];
__device__ float g_Mout[H_ * 2 * F_ * D_];       // [h][p][x][o] irfft+w_out folded, fp32
__device__ float g_aq[(size_t)ROWS_ * H_ * F_];  // |q_ft| [row][h][f]
__device__ float g_ak[(size_t)ROWS_ * H_ * F_];
__device__ float g_attp[B_ * H_ * 4 * F_ * F_];  // partial att sums (4 e-quarters)
__device__ float g_att[B_ * H_ * F_ * F_];       // softmaxed att
__device__ __nv_bfloat16 g_Vhi[(size_t)ROWS_ * NKP_]; // V freq feats (pads stay 0)
__device__ __nv_bfloat16 g_Vlo[(size_t)ROWS_ * NKP_];
__device__ __nv_bfloat16 g_CThi[B_ * D_ * NKP_]; // [b][o][k] folded att@Mout (pads 0)
__device__ __nv_bfloat16 g_CTlo[B_ * D_ * NKP_];

// ---------------- helpers ----------------
__device__ __forceinline__ uint32_t smem_u32(const void* p) {
    uint32_t a;
    asm("{ .reg .u64 t; cvta.to.shared.u64 t, %1; cvt.u32.u64 %0, t; }" : "=r"(a) : "l"(p));
    return a;
}
__device__ __forceinline__ void ldsm_x4(uint32_t* r, uint32_t addr) {
    asm volatile("ldmatrix.sync.aligned.m8n8.x4.shared.b16 {%0,%1,%2,%3}, [%4];"
                 : "=r"(r[0]), "=r"(r[1]), "=r"(r[2]), "=r"(r[3]) : "r"(addr));
}
__device__ __forceinline__ void mma16816(float* c, const uint32_t* a, const uint32_t* b) {
    asm volatile("mma.sync.aligned.m16n8k16.row.col.f32.bf16.bf16.f32 "
                 "{%0,%1,%2,%3}, {%4,%5,%6,%7}, {%8,%9}, {%0,%1,%2,%3};"
                 : "+f"(c[0]), "+f"(c[1]), "+f"(c[2]), "+f"(c[3])
                 : "r"(a[0]), "r"(a[1]), "r"(a[2]), "r"(a[3]), "r"(b[0]), "r"(b[1]));
}
__device__ __forceinline__ uint32_t pack_bf(__nv_bfloat16 a, __nv_bfloat16 b) {
    __nv_bfloat162 p = __halves2bfloat162(a, b);
    return *reinterpret_cast<uint32_t*>(&p);
}
__device__ __forceinline__ uint32_t swz(int row, int colbyte) {
    return (uint32_t)(row * 256 + (colbyte ^ ((row & 7) << 4)));
}

#define SM_AHI  0
#define SM_ALO  32768
#define SM_BHI  65536
#define SM_BLO  98304
#define SM_TOT  131072

// 3-pass (hi*hi + hi*lo + lo*hi) mma sweep over a resident 128x128 K-chunk
__device__ __forceinline__ void mma_chunk(uint32_t sb, int lane, int wm, int wn,
                                          float c[2][8][4]) {
    const uint32_t aoff[3] = {SM_AHI, SM_AHI, SM_ALO};
    const uint32_t boff[3] = {SM_BHI, SM_BLO, SM_BHI};
    #pragma unroll
    for (int p = 0; p < 3; p++) {
        uint32_t sA = sb + aoff[p], sB = sb + boff[p];
        #pragma unroll
        for (int ks = 0; ks < 8; ks++) {
            int colb = ks * 32 + (lane >> 4) * 16;
            uint32_t a[2][4];
            #pragma unroll
            for (int tm = 0; tm < 2; tm++) {
                int r = wm * 32 + tm * 16 + (lane & 15);
                ldsm_x4(a[tm], sA + swz(r, colb));
            }
            uint32_t b[8][2];
            #pragma unroll
            for (int ng = 0; ng < 4; ng++) {
                int n = wn * 64 + ng * 16 + (lane & 15);
                uint32_t q[4];
                ldsm_x4(q, sB + swz(n, colb));
                b[2 * ng][0] = q[0]; b[2 * ng + 1][0] = q[1];
                b[2 * ng][1] = q[2]; b[2 * ng + 1][1] = q[3];
            }
            #pragma unroll
            for (int tm = 0; tm < 2; tm++)
                #pragma unroll
                for (int tn = 0; tn < 8; tn++)
                    mma16816(c[tm][tn], a[tm], b[tn]);
        }
    }
}

// ---------------- weight folding (interleaved re/im: u = 2f + p) ----------------
__global__ void build_w1_kernel(const float* __restrict__ w_qkv) {
    __shared__ float cs[128], sn[128];
    int t = threadIdx.x;
    if (t < 128) {
        float ang = (float)t / 64.0f;
        cs[t] = cospif(ang);
        sn[t] = sinpif(ang);
    }
    __syncthreads();
    const int total = N1P_ * D_;
    for (int idx = blockIdx.x * blockDim.x + t; idx < total; idx += gridDim.x * blockDim.x) {
        int c = idx >> 7, d = idx & 127;
        float acc = 0.f;
        if (c < N1_) {
            int region = c / 1040;
            int cc = c - region * 1040;
            int hd = cc / 130;
            int u = cc - hd * 130;
            int f = u >> 1;
            const float* w = w_qkv + (size_t)d * 3072 + region * 1024 + hd * 128;
            if ((u & 1) == 0) {
                #pragma unroll 8
                for (int dd = 0; dd < 128; dd++) acc += w[dd] * cs[(f * dd) & 127];
            } else {
                #pragma unroll 8
                for (int dd = 0; dd < 128; dd++) acc -= w[dd] * sn[(f * dd) & 127];
            }
            if (region != 2) acc *= SCALE_;
        }
        __nv_bfloat16 hi = __float2bfloat16(acc);
        g_W1T_hi[idx] = hi;
        g_W1T_lo[idx] = __float2bfloat16(acc - __bfloat162float(hi));
    }
}

// g_Mout[((h*2+p)*65 + x)*128 + o], fp32
__global__ void build_mout_kernel(const float* __restrict__ w_out) {
    __shared__ float cs[128], sn[128];
    int t = threadIdx.x;
    if (t < 128) {
        float ang = (float)t / 64.0f;
        cs[t] = cospif(ang);
        sn[t] = sinpif(ang);
    }
    __syncthreads();
    const int total = H_ * 2 * F_ * D_;
    for (int idx = blockIdx.x * blockDim.x + t; idx < total; idx += gridDim.x * blockDim.x) {
        int o = idx & 127;
        int r = idx >> 7;
        int x = r % 65;
        int hp = r / 65;
        int p = hp & 1, hd = hp >> 1;
        float acc = 0.f;
        if (p == 0) {
            #pragma unroll 8
            for (int t2 = 0; t2 < 128; t2++)
                acc += cs[(x * t2) & 127] * w_out[(size_t)(hd * 128 + t2) * 128 + o];
            acc *= ((x == 0 || x == 64) ? 1.0f : 2.0f) / 128.0f;
        } else if (x != 0 && x != 64) {
            #pragma unroll 8
            for (int t2 = 0; t2 < 128; t2++)
                acc -= sn[(x * t2) & 127] * w_out[(size_t)(hd * 128 + t2) * 128 + o];
            acc *= 2.0f / 128.0f;
        }
        g_Mout[idx] = acc;
    }
}

// ---------------- GEMM1: X@W1 -> fused |q|,|k| + V bf16 hi/lo ----------------
__global__ void __launch_bounds__(256, 1) gemm1_tc(const float* __restrict__ X) {
    extern __shared__ char smem[];
    uint32_t sb = smem_u32(smem);
    int tid = threadIdx.x;
    int lane = tid & 31, wid = tid >> 5;
    int wm = wid & 3, wn = wid >> 2;
    int bm = blockIdx.y * 128, bn = blockIdx.x * 128;

    for (int u = tid; u < 4096; u += 256) {
        int r = u >> 5, c4 = (u & 31) * 4;
        float4 v = *(const float4*)(X + (size_t)(bm + r) * 128 + c4);
        __nv_bfloat16 h0 = __float2bfloat16(v.x), h1 = __float2bfloat16(v.y);
        __nv_bfloat16 h2 = __float2bfloat16(v.z), h3 = __float2bfloat16(v.w);
        uint32_t ad = swz(r, c4 * 2);
        *(uint2*)(smem + SM_AHI + ad) = make_uint2(pack_bf(h0, h1), pack_bf(h2, h3));
        *(uint2*)(smem + SM_ALO + ad) = make_uint2(
            pack_bf(__float2bfloat16(v.x - __bfloat162float(h0)),
                    __float2bfloat16(v.y - __bfloat162float(h1))),
            pack_bf(__float2bfloat16(v.z - __bfloat162float(h2)),
                    __float2bfloat16(v.w - __bfloat162float(h3))));
    }
    for (int u = tid; u < 2048; u += 256) {
        int r = u >> 4, c8 = (u & 15) * 8;
        uint32_t ad = swz(r, c8 * 2);
        *(uint4*)(smem + SM_BHI + ad) = *(const uint4*)(g_W1T_hi + (size_t)(bn + r) * 128 + c8);
        *(uint4*)(smem + SM_BLO + ad) = *(const uint4*)(g_W1T_lo + (size_t)(bn + r) * 128 + c8);
    }
    __syncthreads();

    float c[2][8][4];
    #pragma unroll
    for (int i = 0; i < 2; i++)
        #pragma unroll
        for (int j = 0; j < 8; j++)
            #pragma unroll
            for (int k = 0; k < 4; k++) c[i][j][k] = 0.f;

    mma_chunk(sb, lane, wm, wn, c);

    // fused epilogue: pairs (re,im) live in adjacent accumulator slots
    int g = lane >> 2, cp = (lane & 3) * 2;
    #pragma unroll
    for (int tm = 0; tm < 2; tm++)
        #pragma unroll
        for (int hf = 0; hf < 2; hf++) {
            size_t row = (size_t)bm + wm * 32 + tm * 16 + hf * 8 + g;
            #pragma unroll
            for (int tn = 0; tn < 8; tn++) {
                int col = bn + wn * 64 + tn * 8 + cp;   // even
                if (col >= N1_) continue;
                float re = c[tm][tn][hf * 2], im = c[tm][tn][hf * 2 + 1];
                int region = col / 1040;
                int cc = col - region * 1040;
                if (region == 0) {
                    int hd = cc / 130;
                    int f = (cc - hd * 130) >> 1;
                    g_aq[(row * 8 + hd) * 65 + f] = sqrtf(re * re + im * im);
                } else if (region == 1) {
                    int hd = cc / 130;
                    int f = (cc - hd * 130) >> 1;
                    g_ak[(row * 8 + hd) * 65 + f] = sqrtf(re * re + im * im);
                } else {
                    __nv_bfloat16 rh = __float2bfloat16(re), ih = __float2bfloat16(im);
                    __nv_bfloat16 rl = __float2bfloat16(re - __bfloat162float(rh));
                    __nv_bfloat16 il = __float2bfloat16(im - __bfloat162float(ih));
                    size_t off = (row * NKP_ + cc) * 2;   // bytes (cc even -> 4B aligned)
                    *(uint32_t*)((char*)g_Vhi + off) = pack_bf(rh, ih);
                    *(uint32_t*)((char*)g_Vlo + off) = pack_bf(rl, il);
                }
            }
        }
}

// ---------------- att partial: quarter of the e-range ----------------
__global__ void __launch_bounds__(256) att_partial_kernel() {
    __shared__ float sm[8320];
    float* aqs = sm;
    float* aks = sm + 4160;
    int bh = blockIdx.y;
    int b = bh >> 3, h = bh & 7;
    int quarter = blockIdx.x;
    int tid = threadIdx.x;
    int tx = tid & 15, ty = tid >> 4;
    int xs[5], ys[5];
    #pragma unroll
    for (int i = 0; i < 5; i++) {
        int x = tx + 16 * i; xs[i] = (x < 65) ? x : 0;
        int y = ty + 16 * i; ys[i] = (y < 65) ? y : 0;
    }
    float acc[5][5];
    #pragma unroll
    for (int i = 0; i < 5; i++)
        #pragma unroll
        for (int j = 0; j < 5; j++) acc[i][j] = 0.f;

    int ebase = quarter * 512;
    for (int e0 = ebase; e0 < ebase + 512; e0 += 64) {
        for (int idx = tid; idx < 4160; idx += 256) {
            int r = idx / 65, f = idx - r * 65;
            size_t gidx = ((size_t)((b * 2048 + e0 + r) * 8 + h)) * 65 + f;
            aqs[idx] = g_aq[gidx];
            aks[idx] = g_ak[gidx];
        }
        __syncthreads();
        #pragma unroll 4
        for (int e = 0; e < 64; e++) {
            float av[5], bv[5];
            #pragma unroll
            for (int i = 0; i < 5; i++) av[i] = aqs[e * 65 + xs[i]];
            #pragma unroll
            for (int j = 0; j < 5; j++) bv[j] = aks[e * 65 + ys[j]];
            #pragma unroll
            for (int i = 0; i < 5; i++)
                #pragma unroll
                for (int j = 0; j < 5; j++) acc[i][j] += av[i] * bv[j];
        }
        __syncthreads();
    }
    float* dst = g_attp + (size_t)(bh * 4 + quarter) * 4225;
    #pragma unroll
    for (int i = 0; i < 5; i++) {
        int x = tx + 16 * i;
        if (x < 65)
            #pragma unroll
            for (int j = 0; j < 5; j++) {
                int y = ty + 16 * j;
                if (y < 65) dst[x * 65 + y] = acc[i][j];
            }
    }
}

// ---------------- softmax over y after summing partials ----------------
__global__ void __launch_bounds__(256) att_softmax_kernel() {
    __shared__ float sm[4225];
    int bh = blockIdx.x;
    int tid = threadIdx.x;
    const float* p0 = g_attp + (size_t)(bh * 4) * 4225;
    for (int idx = tid; idx < 4225; idx += 256)
        sm[idx] = p0[idx] + p0[4225 + idx] + p0[2 * 4225 + idx] + p0[3 * 4225 + idx];
    __syncthreads();
    int warp = tid >> 5, lane = tid & 31;
    for (int x = warp; x < 65; x += 8) {
        float m = -3.4e38f;
        for (int y = lane; y < 65; y += 32) m = fmaxf(m, sm[x * 65 + y]);
        #pragma unroll
        for (int o = 16; o; o >>= 1) m = fmaxf(m, __shfl_xor_sync(0xffffffffu, m, o));
        float s = 0.f;
        for (int y = lane; y < 65; y += 32) {
            float v = expf(sm[x * 65 + y] - m);
            sm[x * 65 + y] = v;
            s += v;
        }
        #pragma unroll
        for (int o = 16; o; o >>= 1) s += __shfl_xor_sync(0xffffffffu, s, o);
        float inv = 1.0f / s;
        for (int y = lane; y < 65; y += 32)
            g_att[(size_t)bh * 4225 + x * 65 + y] = sm[x * 65 + y] * inv;
    }
}

// ---------------- build C_b: CT[b][o][h*130+2y+p] = sum_x att[x,y]*Mout[h,p,x,o] ----------------
__global__ void __launch_bounds__(256) build_c_kernel() {
    extern __shared__ float csm[];           // att 4225 + mout 8320
    float* att_s = csm;
    float* mout_s = csm + 4225;
    int blk = blockIdx.x;                    // b*16 + h*2 + p
    int b = blk >> 4;
    int hp = blk & 15;
    int hd = hp >> 1, p = hp & 1;
    int tid = threadIdx.x;
    int bh = b * 8 + hd;
    for (int idx = tid; idx < 4225; idx += 256)
        att_s[idx] = g_att[(size_t)bh * 4225 + idx];
    for (int idx = tid; idx < 8320; idx += 256)
        mout_s[idx] = g_Mout[(size_t)hp * 8320 + idx];
    __syncthreads();
    for (int idx = tid; idx < 8320; idx += 256) {
        int o = idx / 65, y = idx - o * 65;
        float acc = 0.f;
        #pragma unroll 5
        for (int x = 0; x < 65; x++)
            acc += att_s[x * 65 + y] * mout_s[x * 128 + o];
        int k = hd * 130 + 2 * y + p;
        __nv_bfloat16 hi = __float2bfloat16(acc);
        size_t off = ((size_t)b * 128 + o) * NKP_ + k;
        g_CThi[off] = hi;
        g_CTlo[off] = __float2bfloat16(acc - __bfloat162float(hi));
    }
}

// ---------------- GEMM2: out = V_b[32768,1152] @ CT_b^T + bias ----------------
__global__ void __launch_bounds__(256, 1) gemm2_tc(float* __restrict__ out,
                                                   const float* __restrict__ bias) {
    extern __shared__ char smem[];
    uint32_t sb = smem_u32(smem);
    int tid = threadIdx.x;
    int lane = tid & 31, wid = tid >> 5;
    int wm = wid & 3, wn = wid >> 2;
    int bm = blockIdx.y * 128;
    int b = bm >> 11;
    const __nv_bfloat16* CThi = g_CThi + (size_t)b * 128 * NKP_;
    const __nv_bfloat16* CTlo = g_CTlo + (size_t)b * 128 * NKP_;

    float c[2][8][4];
    #pragma unroll
    for (int i = 0; i < 2; i++)
        #pragma unroll
        for (int j = 0; j < 8; j++)
            #pragma unroll
            for (int k = 0; k < 4; k++) c[i][j][k] = 0.f;

    for (int kc = 0; kc < 9; kc++) {
        int k0 = kc * 128;
        __syncthreads();
        for (int u = tid; u < 2048; u += 256) {
            int r = u >> 4, c8 = (u & 15) * 8;
            uint32_t ad = swz(r, c8 * 2);
            *(uint4*)(smem + SM_AHI + ad) = *(const uint4*)(g_Vhi + (size_t)(bm + r) * NKP_ + k0 + c8);
            *(uint4*)(smem + SM_ALO + ad) = *(const uint4*)(g_Vlo + (size_t)(bm + r) * NKP_ + k0 + c8);
            *(uint4*)(smem + SM_BHI + ad) = *(const uint4*)(CThi + (size_t)r * NKP_ + k0 + c8);
            *(uint4*)(smem + SM_BLO + ad) = *(const uint4*)(CTlo + (size_t)r * NKP_ + k0 + c8);
        }
        __syncthreads();
        mma_chunk(sb, lane, wm, wn, c);
    }

    int g = lane >> 2, cp = (lane & 3) * 2;
    #pragma unroll
    for (int tm = 0; tm < 2; tm++)
        #pragma unroll
        for (int hf = 0; hf < 2; hf++) {
            size_t row = (size_t)bm + wm * 32 + tm * 16 + hf * 8 + g;
            float* dst = out + row * 128;
            #pragma unroll
            for (int tn = 0; tn < 8; tn++) {
                int col = wn * 64 + tn * 8 + cp;
                float2 bv = *(const float2*)(bias + col);
                *(float2*)(dst + col) = make_float2(c[tm][tn][hf * 2] + bv.x,
                                                    c[tm][tn][hf * 2 + 1] + bv.y);
            }
        }
}

// ---------------- launch ----------------
extern "C" void kernel_launch(void* const* d_in, const int* in_sizes, int n_in,
                              void* d_out, int out_size) {
    const float* x     = (const float*)d_in[0];
    const float* w_qkv = (const float*)d_in[1];
    const float* w_out = (const float*)d_in[2];
    const float* b_out = (const float*)d_in[3];
    float* out = (float*)d_out;

    cudaFuncSetAttribute(gemm1_tc, cudaFuncAttributeMaxDynamicSharedMemorySize, SM_TOT);
    cudaFuncSetAttribute(gemm2_tc, cudaFuncAttributeMaxDynamicSharedMemorySize, SM_TOT);
    cudaFuncSetAttribute(build_c_kernel, cudaFuncAttributeMaxDynamicSharedMemorySize,
                         (4225 + 8320) * 4);

    build_w1_kernel<<<480, 256>>>(w_qkv);
    build_mout_kernel<<<130, 256>>>(w_out);
    gemm1_tc<<<dim3(N1P_ / 128, ROWS_ / 128), 256, SM_TOT>>>(x);
    att_partial_kernel<<<dim3(4, B_ * H_), 256>>>();
    att_softmax_kernel<<<B_ * H_, 256>>>();
    build_c_kernel<<<B_ * H_ * 2, 256, (4225 + 8320) * 4>>>();
    gemm2_tc<<<dim3(1, ROWS_ / 128), 256, SM_TOT>>>(out, b_out);
}

// round 5
// speedup vs baseline: 1.7582x; 1.3202x over previous
#include <cuda_runtime.h>
#include <cuda_bf16.h>
#include <cstdint>
#include <math.h>

// Problem constants
#define B_    16
#define N_    2048
#define D_    128
#define H_    8
#define F_    65
#define ROWS_ 32768
#define N1_   3120       // q,k,v * 8 heads * 130 (re/im interleaved: u = 2f+p)
#define N1P_  3200       // padded to 25*128
#define NK_   1040       // 8 * 130 (V feature dim = gemm2 K)
#define NKP_  1152       // padded to 9*128
#define SCALE_ (1.0f/65.0f)

// ---------------- scratch (static device, no allocation) ----------------
__device__ __nv_bfloat16 g_Xhi[(size_t)ROWS_ * D_];   // pre-split input
__device__ __nv_bfloat16 g_Xlo[(size_t)ROWS_ * D_];
__device__ __nv_bfloat16 g_W1T_hi[N1P_ * D_];    // [3200][128] gemm1 B (n-major, k contig)
__device__ __nv_bfloat16 g_W1T_lo[N1P_ * D_];
__device__ float g_Mout[H_ * 2 * F_ * D_];       // [h][p][x][o] irfft+w_out folded
__device__ float g_aq[(size_t)ROWS_ * H_ * F_];  // |q_ft| [row][h][f]
__device__ float g_ak[(size_t)ROWS_ * H_ * F_];
__device__ float g_attp[B_ * H_ * 4 * F_ * F_];  // partial att sums
__device__ float g_att[B_ * H_ * F_ * F_];
__device__ __nv_bfloat16 g_Vhi[(size_t)ROWS_ * NKP_]; // pads stay 0
__device__ __nv_bfloat16 g_Vlo[(size_t)ROWS_ * NKP_];
__device__ __nv_bfloat16 g_CThi[B_ * D_ * NKP_]; // [b][o][k], pads 0
__device__ __nv_bfloat16 g_CTlo[B_ * D_ * NKP_];

// ---------------- helpers ----------------
__device__ __forceinline__ uint32_t smem_u32(const void* p) {
    uint32_t a;
    asm("{ .reg .u64 t; cvta.to.shared.u64 t, %1; cvt.u32.u64 %0, t; }" : "=r"(a) : "l"(p));
    return a;
}
__device__ __forceinline__ void ldsm_x4(uint32_t* r, uint32_t addr) {
    asm volatile("ldmatrix.sync.aligned.m8n8.x4.shared.b16 {%0,%1,%2,%3}, [%4];"
                 : "=r"(r[0]), "=r"(r[1]), "=r"(r[2]), "=r"(r[3]) : "r"(addr));
}
__device__ __forceinline__ void mma16816(float* c, const uint32_t* a, const uint32_t* b) {
    asm volatile("mma.sync.aligned.m16n8k16.row.col.f32.bf16.bf16.f32 "
                 "{%0,%1,%2,%3}, {%4,%5,%6,%7}, {%8,%9}, {%0,%1,%2,%3};"
                 : "+f"(c[0]), "+f"(c[1]), "+f"(c[2]), "+f"(c[3])
                 : "r"(a[0]), "r"(a[1]), "r"(a[2]), "r"(a[3]), "r"(b[0]), "r"(b[1]));
}
__device__ __forceinline__ uint32_t pack_bf(__nv_bfloat16 a, __nv_bfloat16 b) {
    __nv_bfloat162 p = __halves2bfloat162(a, b);
    return *reinterpret_cast<uint32_t*>(&p);
}
// swizzled offset within a [rows][64 bf16] tile (row = 128 bytes)
__device__ __forceinline__ uint32_t swz64(int row, int colbyte) {
    return (uint32_t)(row * 128 + (colbyte ^ ((row & 7) << 4)));
}
__device__ __forceinline__ void cp16(uint32_t dst, const void* src) {
    asm volatile("cp.async.cg.shared.global [%0], [%1], 16;" :: "r"(dst), "l"(src));
}
__device__ __forceinline__ void cp_commit() { asm volatile("cp.async.commit_group;"); }
__device__ __forceinline__ void cp_wait0() { asm volatile("cp.async.wait_group 0;" ::: "memory"); }
__device__ __forceinline__ void cp_wait1() { asm volatile("cp.async.wait_group 1;" ::: "memory"); }

// 3-pass mma sweep over one resident [*x64] K-chunk (4 k-steps)
__device__ __forceinline__ void mma_chunk64(uint32_t sAhi, uint32_t sAlo,
                                            uint32_t sBhi, uint32_t sBlo,
                                            int lane, int wm, int wn, float c[2][8][4]) {
    #pragma unroll
    for (int p = 0; p < 3; p++) {
        uint32_t sA = (p == 2) ? sAlo : sAhi;
        uint32_t sB = (p == 1) ? sBlo : sBhi;
        #pragma unroll
        for (int ks = 0; ks < 4; ks++) {
            int colb = ks * 32 + (lane >> 4) * 16;
            uint32_t a[2][4];
            #pragma unroll
            for (int tm = 0; tm < 2; tm++) {
                int r = wm * 32 + tm * 16 + (lane & 15);
                ldsm_x4(a[tm], sA + swz64(r, colb));
            }
            uint32_t b[8][2];
            #pragma unroll
            for (int ng = 0; ng < 4; ng++) {
                int n = wn * 64 + ng * 16 + (lane & 15);
                uint32_t q[4];
                ldsm_x4(q, sB + swz64(n, colb));
                b[2 * ng][0] = q[0]; b[2 * ng + 1][0] = q[1];
                b[2 * ng][1] = q[2]; b[2 * ng + 1][1] = q[3];
            }
            #pragma unroll
            for (int tm = 0; tm < 2; tm++)
                #pragma unroll
                for (int tn = 0; tn < 8; tn++)
                    mma16816(c[tm][tn], a[tm], b[tn]);
        }
    }
}

// ---------------- X pre-split ----------------
__global__ void split_x_kernel(const float* __restrict__ X) {
    size_t i = (size_t)blockIdx.x * blockDim.x + threadIdx.x;   // over ROWS_*D_/4
    float4 v = ((const float4*)X)[i];
    __nv_bfloat16 h0 = __float2bfloat16(v.x), h1 = __float2bfloat16(v.y);
    __nv_bfloat16 h2 = __float2bfloat16(v.z), h3 = __float2bfloat16(v.w);
    ((uint2*)g_Xhi)[i] = make_uint2(pack_bf(h0, h1), pack_bf(h2, h3));
    ((uint2*)g_Xlo)[i] = make_uint2(
        pack_bf(__float2bfloat16(v.x - __bfloat162float(h0)),
                __float2bfloat16(v.y - __bfloat162float(h1))),
        pack_bf(__float2bfloat16(v.z - __bfloat162float(h2)),
                __float2bfloat16(v.w - __bfloat162float(h3))));
}

// ---------------- weight folding (interleaved re/im: u = 2f + p) ----------------
__global__ void build_w1_kernel(const float* __restrict__ w_qkv) {
    __shared__ float cs[128], sn[128];
    int t = threadIdx.x;
    if (t < 128) {
        float ang = (float)t / 64.0f;
        cs[t] = cospif(ang);
        sn[t] = sinpif(ang);
    }
    __syncthreads();
    const int total = N1P_ * D_;
    for (int idx = blockIdx.x * blockDim.x + t; idx < total; idx += gridDim.x * blockDim.x) {
        int c = idx >> 7, d = idx & 127;
        float acc = 0.f;
        if (c < N1_) {
            int region = c / 1040;
            int cc = c - region * 1040;
            int hd = cc / 130;
            int u = cc - hd * 130;
            int f = u >> 1;
            const float* w = w_qkv + (size_t)d * 3072 + region * 1024 + hd * 128;
            if ((u & 1) == 0) {
                #pragma unroll 8
                for (int dd = 0; dd < 128; dd++) acc += w[dd] * cs[(f * dd) & 127];
            } else {
                #pragma unroll 8
                for (int dd = 0; dd < 128; dd++) acc -= w[dd] * sn[(f * dd) & 127];
            }
            if (region != 2) acc *= SCALE_;
        }
        __nv_bfloat16 hi = __float2bfloat16(acc);
        g_W1T_hi[idx] = hi;
        g_W1T_lo[idx] = __float2bfloat16(acc - __bfloat162float(hi));
    }
}

__global__ void build_mout_kernel(const float* __restrict__ w_out) {
    __shared__ float cs[128], sn[128];
    int t = threadIdx.x;
    if (t < 128) {
        float ang = (float)t / 64.0f;
        cs[t] = cospif(ang);
        sn[t] = sinpif(ang);
    }
    __syncthreads();
    const int total = H_ * 2 * F_ * D_;
    for (int idx = blockIdx.x * blockDim.x + t; idx < total; idx += gridDim.x * blockDim.x) {
        int o = idx & 127;
        int r = idx >> 7;
        int x = r % 65;
        int hp = r / 65;
        int p = hp & 1, hd = hp >> 1;
        float acc = 0.f;
        if (p == 0) {
            #pragma unroll 8
            for (int t2 = 0; t2 < 128; t2++)
                acc += cs[(x * t2) & 127] * w_out[(size_t)(hd * 128 + t2) * 128 + o];
            acc *= ((x == 0 || x == 64) ? 1.0f : 2.0f) / 128.0f;
        } else if (x != 0 && x != 64) {
            #pragma unroll 8
            for (int t2 = 0; t2 < 128; t2++)
                acc -= sn[(x * t2) & 127] * w_out[(size_t)(hd * 128 + t2) * 128 + o];
            acc *= 2.0f / 128.0f;
        }
        g_Mout[idx] = acc;
    }
}

// ---------------- GEMM1: X@W1 (pipelined) -> fused |q|,|k| + V bf16 hi/lo ----------------
// stage: AHI 16K @0, ALO @16384, BHI @32768, BLO @49152; stride 65536
__device__ __forceinline__ void g1_load(uint32_t sst, int bm, int bn, int k0, int tid) {
    #pragma unroll
    for (int u = tid; u < 1024; u += 256) {
        int r = u >> 3, cb = (u & 7) * 16;
        uint32_t d = swz64(r, cb);
        const char* sa = (const char*)g_Xhi + ((size_t)(bm + r) * 128 + k0) * 2 + cb;
        const char* sb = (const char*)g_W1T_hi + ((size_t)(bn + r) * 128 + k0) * 2 + cb;
        cp16(sst + d, sa);
        cp16(sst + 16384 + d, sa + (size_t)ROWS_ * D_ * 2 - ((const char*)g_Xhi - (const char*)g_Xhi));
        // note: lo buffers are distinct symbols; compute real addresses:
        cp16(sst + 16384 + d, (const char*)g_Xlo + ((size_t)(bm + r) * 128 + k0) * 2 + cb);
        cp16(sst + 32768 + d, sb);
        cp16(sst + 49152 + d, (const char*)g_W1T_lo + ((size_t)(bn + r) * 128 + k0) * 2 + cb);
    }
}

__global__ void __launch_bounds__(256, 1) gemm1_tc() {
    extern __shared__ char smem[];
    uint32_t sb = smem_u32(smem);
    int tid = threadIdx.x;
    int lane = tid & 31, wid = tid >> 5;
    int wm = wid & 3, wn = wid >> 2;
    int bm = blockIdx.y * 128, bn = blockIdx.x * 128;

    g1_load(sb, bm, bn, 0, tid);  cp_commit();
    g1_load(sb + 65536, bm, bn, 64, tid);  cp_commit();

    float c[2][8][4];
    #pragma unroll
    for (int i = 0; i < 2; i++)
        #pragma unroll
        for (int j = 0; j < 8; j++)
            #pragma unroll
            for (int k = 0; k < 4; k++) c[i][j][k] = 0.f;

    cp_wait1();
    __syncthreads();
    mma_chunk64(sb, sb + 16384, sb + 32768, sb + 49152, lane, wm, wn, c);
    cp_wait0();
    __syncthreads();
    mma_chunk64(sb + 65536, sb + 81920, sb + 98304, sb + 114688, lane, wm, wn, c);

    // fused epilogue: (re,im) adjacent in accumulator slots
    int g = lane >> 2, cp = (lane & 3) * 2;
    #pragma unroll
    for (int tm = 0; tm < 2; tm++)
        #pragma unroll
        for (int hf = 0; hf < 2; hf++) {
            size_t row = (size_t)bm + wm * 32 + tm * 16 + hf * 8 + g;
            #pragma unroll
            for (int tn = 0; tn < 8; tn++) {
                int col = bn + wn * 64 + tn * 8 + cp;   // even
                if (col >= N1_) continue;
                float re = c[tm][tn][hf * 2], im = c[tm][tn][hf * 2 + 1];
                int region = col / 1040;
                int cc = col - region * 1040;
                if (region == 0) {
                    int hd = cc / 130;
                    int f = (cc - hd * 130) >> 1;
                    g_aq[(row * 8 + hd) * 65 + f] = sqrtf(re * re + im * im);
                } else if (region == 1) {
                    int hd = cc / 130;
                    int f = (cc - hd * 130) >> 1;
                    g_ak[(row * 8 + hd) * 65 + f] = sqrtf(re * re + im * im);
                } else {
                    __nv_bfloat16 rh = __float2bfloat16(re), ih = __float2bfloat16(im);
                    __nv_bfloat16 rl = __float2bfloat16(re - __bfloat162float(rh));
                    __nv_bfloat16 il = __float2bfloat16(im - __bfloat162float(ih));
                    size_t off = (row * NKP_ + cc) * 2;   // bytes
                    *(uint32_t*)((char*)g_Vhi + off) = pack_bf(rh, ih);
                    *(uint32_t*)((char*)g_Vlo + off) = pack_bf(rl, il);
                }
            }
        }
}

// ---------------- att partial ----------------
__global__ void __launch_bounds__(256) att_partial_kernel() {
    __shared__ float sm[8320];
    float* aqs = sm;
    float* aks = sm + 4160;
    int bh = blockIdx.y;
    int b = bh >> 3, h = bh & 7;
    int quarter = blockIdx.x;
    int tid = threadIdx.x;
    int tx = tid & 15, ty = tid >> 4;
    int xs[5], ys[5];
    #pragma unroll
    for (int i = 0; i < 5; i++) {
        int x = tx + 16 * i; xs[i] = (x < 65) ? x : 0;
        int y = ty + 16 * i; ys[i] = (y < 65) ? y : 0;
    }
    float acc[5][5];
    #pragma unroll
    for (int i = 0; i < 5; i++)
        #pragma unroll
        for (int j = 0; j < 5; j++) acc[i][j] = 0.f;

    int ebase = quarter * 512;
    for (int e0 = ebase; e0 < ebase + 512; e0 += 64) {
        for (int idx = tid; idx < 4160; idx += 256) {
            int r = idx / 65, f = idx - r * 65;
            size_t gidx = ((size_t)((b * 2048 + e0 + r) * 8 + h)) * 65 + f;
            aqs[idx] = g_aq[gidx];
            aks[idx] = g_ak[gidx];
        }
        __syncthreads();
        #pragma unroll 4
        for (int e = 0; e < 64; e++) {
            float av[5], bv[5];
            #pragma unroll
            for (int i = 0; i < 5; i++) av[i] = aqs[e * 65 + xs[i]];
            #pragma unroll
            for (int j = 0; j < 5; j++) bv[j] = aks[e * 65 + ys[j]];
            #pragma unroll
            for (int i = 0; i < 5; i++)
                #pragma unroll
                for (int j = 0; j < 5; j++) acc[i][j] += av[i] * bv[j];
        }
        __syncthreads();
    }
    float* dst = g_attp + (size_t)(bh * 4 + quarter) * 4225;
    #pragma unroll
    for (int i = 0; i < 5; i++) {
        int x = tx + 16 * i;
        if (x < 65)
            #pragma unroll
            for (int j = 0; j < 5; j++) {
                int y = ty + 16 * j;
                if (y < 65) dst[x * 65 + y] = acc[i][j];
            }
    }
}

// ---------------- softmax ----------------
__global__ void __launch_bounds__(256) att_softmax_kernel() {
    __shared__ float sm[4225];
    int bh = blockIdx.x;
    int tid = threadIdx.x;
    const float* p0 = g_attp + (size_t)(bh * 4) * 4225;
    for (int idx = tid; idx < 4225; idx += 256)
        sm[idx] = p0[idx] + p0[4225 + idx] + p0[2 * 4225 + idx] + p0[3 * 4225 + idx];
    __syncthreads();
    int warp = tid >> 5, lane = tid & 31;
    for (int x = warp; x < 65; x += 8) {
        float m = -3.4e38f;
        for (int y = lane; y < 65; y += 32) m = fmaxf(m, sm[x * 65 + y]);
        #pragma unroll
        for (int o = 16; o; o >>= 1) m = fmaxf(m, __shfl_xor_sync(0xffffffffu, m, o));
        float s = 0.f;
        for (int y = lane; y < 65; y += 32) {
            float v = expf(sm[x * 65 + y] - m);
            sm[x * 65 + y] = v;
            s += v;
        }
        #pragma unroll
        for (int o = 16; o; o >>= 1) s += __shfl_xor_sync(0xffffffffu, s, o);
        float inv = 1.0f / s;
        for (int y = lane; y < 65; y += 32)
            g_att[(size_t)bh * 4225 + x * 65 + y] = sm[x * 65 + y] * inv;
    }
}

// ---------------- build C_b ----------------
__global__ void __launch_bounds__(256) build_c_kernel() {
    extern __shared__ float csm[];           // att 4225 + mout 8320
    float* att_s = csm;
    float* mout_s = csm + 4225;
    int blk = blockIdx.x;                    // b*16 + h*2 + p
    int b = blk >> 4;
    int hp = blk & 15;
    int hd = hp >> 1, p = hp & 1;
    int tid = threadIdx.x;
    int bh = b * 8 + hd;
    for (int idx = tid; idx < 4225; idx += 256)
        att_s[idx] = g_att[(size_t)bh * 4225 + idx];
    for (int idx = tid; idx < 8320; idx += 256)
        mout_s[idx] = g_Mout[(size_t)hp * 8320 + idx];
    __syncthreads();
    for (int idx = tid; idx < 8320; idx += 256) {
        int o = idx / 65, y = idx - o * 65;
        float acc = 0.f;
        #pragma unroll 5
        for (int x = 0; x < 65; x++)
            acc += att_s[x * 65 + y] * mout_s[x * 128 + o];
        int k = hd * 130 + 2 * y + p;
        __nv_bfloat16 hi = __float2bfloat16(acc);
        size_t off = ((size_t)b * 128 + o) * NKP_ + k;
        g_CThi[off] = hi;
        g_CTlo[off] = __float2bfloat16(acc - __bfloat162float(hi));
    }
}

// ---------------- GEMM2: out = V_b @ CT_b^T + bias (M-tile 256, pipelined) ----------------
// stage: AHI 32K @0, ALO @32768, BHI @65536, BLO @81920; stride 98304
__device__ __forceinline__ void g2_load(uint32_t sst, int bm,
                                        const __nv_bfloat16* CThi,
                                        const __nv_bfloat16* CTlo,
                                        int k0, int tid) {
    #pragma unroll
    for (int u = tid; u < 2048; u += 512) {
        int r = u >> 3, cb = (u & 7) * 16;
        uint32_t d = swz64(r, cb);
        cp16(sst + d, (const char*)g_Vhi + ((size_t)(bm + r) * NKP_ + k0) * 2 + cb);
        cp16(sst + 32768 + d, (const char*)g_Vlo + ((size_t)(bm + r) * NKP_ + k0) * 2 + cb);
    }
    #pragma unroll
    for (int u = tid; u < 1024; u += 512) {
        int r = u >> 3, cb = (u & 7) * 16;
        uint32_t d = swz64(r, cb);
        cp16(sst + 65536 + d, (const char*)CThi + ((size_t)r * NKP_ + k0) * 2 + cb);
        cp16(sst + 81920 + d, (const char*)CTlo + ((size_t)r * NKP_ + k0) * 2 + cb);
    }
}

__global__ void __launch_bounds__(512, 1) gemm2_tc(float* __restrict__ out,
                                                   const float* __restrict__ bias) {
    extern __shared__ char smem[];
    uint32_t sb = smem_u32(smem);
    int tid = threadIdx.x;
    int lane = tid & 31, wid = tid >> 5;
    int wm = wid & 7, wn = wid >> 3;     // 8 x 2 warps over 256 x 128
    int bm = blockIdx.x * 256;
    int b = bm >> 11;
    const __nv_bfloat16* CThi = g_CThi + (size_t)b * 128 * NKP_;
    const __nv_bfloat16* CTlo = g_CTlo + (size_t)b * 128 * NKP_;

    float c[2][8][4];
    #pragma unroll
    for (int i = 0; i < 2; i++)
        #pragma unroll
        for (int j = 0; j < 8; j++)
            #pragma unroll
            for (int k = 0; k < 4; k++) c[i][j][k] = 0.f;

    g2_load(sb, bm, CThi, CTlo, 0, tid);  cp_commit();
    g2_load(sb + 98304, bm, CThi, CTlo, 64, tid);  cp_commit();

    for (int kc = 0; kc < 18; kc++) {
        if (kc < 17) cp_wait1(); else cp_wait0();
        __syncthreads();
        uint32_t sst = sb + (kc & 1) * 98304;
        mma_chunk64(sst, sst + 32768, sst + 65536, sst + 81920, lane, wm, wn, c);
        __syncthreads();
        if (kc + 2 < 18) {
            g2_load(sst, bm, CThi, CTlo, (kc + 2) * 64, tid);
            cp_commit();
        }
    }

    int g = lane >> 2, cp = (lane & 3) * 2;
    #pragma unroll
    for (int tm = 0; tm < 2; tm++)
        #pragma unroll
        for (int hf = 0; hf < 2; hf++) {
            size_t row = (size_t)bm + wm * 32 + tm * 16 + hf * 8 + g;
            float* dst = out + row * 128;
            #pragma unroll
            for (int tn = 0; tn < 8; tn++) {
                int col = wn * 64 + tn * 8 + cp;
                float2 bv = *(const float2*)(bias + col);
                *(float2*)(dst + col) = make_float2(c[tm][tn][hf * 2] + bv.x,
                                                    c[tm][tn][hf * 2 + 1] + bv.y);
            }
        }
}

// ---------------- launch ----------------
extern "C" void kernel_launch(void* const* d_in, const int* in_sizes, int n_in,
                              void* d_out, int out_size) {
    const float* x     = (const float*)d_in[0];
    const float* w_qkv = (const float*)d_in[1];
    const float* w_out = (const float*)d_in[2];
    const float* b_out = (const float*)d_in[3];
    float* out = (float*)d_out;

    cudaFuncSetAttribute(gemm1_tc, cudaFuncAttributeMaxDynamicSharedMemorySize, 131072);
    cudaFuncSetAttribute(gemm2_tc, cudaFuncAttributeMaxDynamicSharedMemorySize, 196608);
    cudaFuncSetAttribute(build_c_kernel, cudaFuncAttributeMaxDynamicSharedMemorySize,
                         (4225 + 8320) * 4);

    split_x_kernel<<<ROWS_ * D_ / 4 / 256, 256>>>(x);
    build_w1_kernel<<<480, 256>>>(w_qkv);
    build_mout_kernel<<<130, 256>>>(w_out);
    gemm1_tc<<<dim3(N1P_ / 128, ROWS_ / 128), 256, 131072>>>();
    att_partial_kernel<<<dim3(4, B_ * H_), 256>>>();
    att_softmax_kernel<<<B_ * H_, 256>>>();
    build_c_kernel<<<B_ * H_ * 2, 256, (4225 + 8320) * 4>>>();
    gemm2_tc<<<ROWS_ / 256, 512, 196608>>>(out, b_out);
}

// round 6
// speedup vs baseline: 1.8361x; 1.0443x over previous
#include <cuda_runtime.h>
#include <cuda_bf16.h>
#include <cstdint>
#include <math.h>

// Problem constants
#define B_    16
#define N_    2048
#define D_    128
#define H_    8
#define F_    65
#define ROWS_ 32768
#define N1_   3120       // q,k,v * 8 heads * 130 (re/im interleaved: u = 2f+p)
#define N1P_  3200       // padded to 25*128
#define NK_   1040       // 8 * 130 (V feature dim = gemm2 K)
#define NKP_  1152       // padded to 9*128
#define SCALE_ (1.0f/65.0f)
#define EQ_   8          // att e-chunks

// ---------------- scratch (static device, no allocation) ----------------
__device__ __nv_bfloat16 g_Xhi[(size_t)ROWS_ * D_];
__device__ __nv_bfloat16 g_Xlo[(size_t)ROWS_ * D_];
__device__ __nv_bfloat16 g_W1T_hi[N1P_ * D_];    // [3200][128]
__device__ __nv_bfloat16 g_W1T_lo[N1P_ * D_];
__device__ float g_Mout[H_ * 2 * F_ * D_];       // [h][p][x][o]
__device__ float g_aq[(size_t)ROWS_ * H_ * F_];
__device__ float g_ak[(size_t)ROWS_ * H_ * F_];
__device__ float g_attp[B_ * H_ * EQ_ * F_ * F_];
__device__ float g_att[B_ * H_ * F_ * F_];
__device__ __nv_bfloat16 g_Vhi[(size_t)ROWS_ * NKP_]; // pads stay 0
__device__ __nv_bfloat16 g_Vlo[(size_t)ROWS_ * NKP_];
__device__ __nv_bfloat16 g_CThi[B_ * D_ * NKP_];
__device__ __nv_bfloat16 g_CTlo[B_ * D_ * NKP_];

// ---------------- helpers ----------------
__device__ __forceinline__ uint32_t smem_u32(const void* p) {
    uint32_t a;
    asm("{ .reg .u64 t; cvta.to.shared.u64 t, %1; cvt.u32.u64 %0, t; }" : "=r"(a) : "l"(p));
    return a;
}
__device__ __forceinline__ void ldsm_x4(uint32_t* r, uint32_t addr) {
    asm volatile("ldmatrix.sync.aligned.m8n8.x4.shared.b16 {%0,%1,%2,%3}, [%4];"
                 : "=r"(r[0]), "=r"(r[1]), "=r"(r[2]), "=r"(r[3]) : "r"(addr));
}
__device__ __forceinline__ void mma16816(float* c, const uint32_t* a, const uint32_t* b) {
    asm volatile("mma.sync.aligned.m16n8k16.row.col.f32.bf16.bf16.f32 "
                 "{%0,%1,%2,%3}, {%4,%5,%6,%7}, {%8,%9}, {%0,%1,%2,%3};"
                 : "+f"(c[0]), "+f"(c[1]), "+f"(c[2]), "+f"(c[3])
                 : "r"(a[0]), "r"(a[1]), "r"(a[2]), "r"(a[3]), "r"(b[0]), "r"(b[1]));
}
__device__ __forceinline__ uint32_t pack_bf(__nv_bfloat16 a, __nv_bfloat16 b) {
    __nv_bfloat162 p = __halves2bfloat162(a, b);
    return *reinterpret_cast<uint32_t*>(&p);
}
// swizzled offset within a [rows][64 bf16] tile (row = 128 bytes)
__device__ __forceinline__ uint32_t swz64(int row, int colbyte) {
    return (uint32_t)(row * 128 + (colbyte ^ ((row & 7) << 4)));
}
__device__ __forceinline__ void cp16(uint32_t dst, const void* src) {
    asm volatile("cp.async.cg.shared.global [%0], [%1], 16;" :: "r"(dst), "l"(src));
}
__device__ __forceinline__ void cp_commit() { asm volatile("cp.async.commit_group;"); }
__device__ __forceinline__ void cp_wait0() { asm volatile("cp.async.wait_group 0;" ::: "memory"); }
__device__ __forceinline__ void cp_wait1() { asm volatile("cp.async.wait_group 1;" ::: "memory"); }

// 3-pass mma sweep over one resident [*x64] K-chunk (4 k-steps)
__device__ __forceinline__ void mma_chunk64(uint32_t sAhi, uint32_t sAlo,
                                            uint32_t sBhi, uint32_t sBlo,
                                            int lane, int wm, int wn, float c[2][8][4]) {
    #pragma unroll
    for (int p = 0; p < 3; p++) {
        uint32_t sA = (p == 2) ? sAlo : sAhi;
        uint32_t sB = (p == 1) ? sBlo : sBhi;
        #pragma unroll
        for (int ks = 0; ks < 4; ks++) {
            int colb = ks * 32 + (lane >> 4) * 16;
            uint32_t a[2][4];
            #pragma unroll
            for (int tm = 0; tm < 2; tm++) {
                int r = wm * 32 + tm * 16 + (lane & 15);
                ldsm_x4(a[tm], sA + swz64(r, colb));
            }
            uint32_t b[8][2];
            #pragma unroll
            for (int ng = 0; ng < 4; ng++) {
                int n = wn * 64 + ng * 16 + (lane & 15);
                uint32_t q[4];
                ldsm_x4(q, sB + swz64(n, colb));
                b[2 * ng][0] = q[0]; b[2 * ng + 1][0] = q[1];
                b[2 * ng][1] = q[2]; b[2 * ng + 1][1] = q[3];
            }
            #pragma unroll
            for (int tm = 0; tm < 2; tm++)
                #pragma unroll
                for (int tn = 0; tn < 8; tn++)
                    mma16816(c[tm][tn], a[tm], b[tn]);
        }
    }
}

// ---------------- X pre-split ----------------
__global__ void split_x_kernel(const float* __restrict__ X) {
    size_t i = (size_t)blockIdx.x * blockDim.x + threadIdx.x;
    float4 v = ((const float4*)X)[i];
    __nv_bfloat16 h0 = __float2bfloat16(v.x), h1 = __float2bfloat16(v.y);
    __nv_bfloat16 h2 = __float2bfloat16(v.z), h3 = __float2bfloat16(v.w);
    ((uint2*)g_Xhi)[i] = make_uint2(pack_bf(h0, h1), pack_bf(h2, h3));
    ((uint2*)g_Xlo)[i] = make_uint2(
        pack_bf(__float2bfloat16(v.x - __bfloat162float(h0)),
                __float2bfloat16(v.y - __bfloat162float(h1))),
        pack_bf(__float2bfloat16(v.z - __bfloat162float(h2)),
                __float2bfloat16(v.w - __bfloat162float(h3))));
}

// ---------------- weight folding (interleaved re/im: u = 2f + p) ----------------
__global__ void build_w1_kernel(const float* __restrict__ w_qkv) {
    __shared__ float cs[128], sn[128];
    int t = threadIdx.x;
    if (t < 128) {
        float ang = (float)t / 64.0f;
        cs[t] = cospif(ang);
        sn[t] = sinpif(ang);
    }
    __syncthreads();
    const int total = N1P_ * D_;
    for (int idx = blockIdx.x * blockDim.x + t; idx < total; idx += gridDim.x * blockDim.x) {
        int c = idx >> 7, d = idx & 127;
        float acc = 0.f;
        if (c < N1_) {
            int region = c / 1040;
            int cc = c - region * 1040;
            int hd = cc / 130;
            int u = cc - hd * 130;
            int f = u >> 1;
            const float* w = w_qkv + (size_t)d * 3072 + region * 1024 + hd * 128;
            if ((u & 1) == 0) {
                #pragma unroll 8
                for (int dd = 0; dd < 128; dd++) acc += w[dd] * cs[(f * dd) & 127];
            } else {
                #pragma unroll 8
                for (int dd = 0; dd < 128; dd++) acc -= w[dd] * sn[(f * dd) & 127];
            }
            if (region != 2) acc *= SCALE_;
        }
        __nv_bfloat16 hi = __float2bfloat16(acc);
        g_W1T_hi[idx] = hi;
        g_W1T_lo[idx] = __float2bfloat16(acc - __bfloat162float(hi));
    }
}

__global__ void build_mout_kernel(const float* __restrict__ w_out) {
    __shared__ float cs[128], sn[128];
    int t = threadIdx.x;
    if (t < 128) {
        float ang = (float)t / 64.0f;
        cs[t] = cospif(ang);
        sn[t] = sinpif(ang);
    }
    __syncthreads();
    const int total = H_ * 2 * F_ * D_;
    for (int idx = blockIdx.x * blockDim.x + t; idx < total; idx += gridDim.x * blockDim.x) {
        int o = idx & 127;
        int r = idx >> 7;
        int x = r % 65;
        int hp = r / 65;
        int p = hp & 1, hd = hp >> 1;
        float acc = 0.f;
        if (p == 0) {
            #pragma unroll 8
            for (int t2 = 0; t2 < 128; t2++)
                acc += cs[(x * t2) & 127] * w_out[(size_t)(hd * 128 + t2) * 128 + o];
            acc *= ((x == 0 || x == 64) ? 1.0f : 2.0f) / 128.0f;
        } else if (x != 0 && x != 64) {
            #pragma unroll 8
            for (int t2 = 0; t2 < 128; t2++)
                acc -= sn[(x * t2) & 127] * w_out[(size_t)(hd * 128 + t2) * 128 + o];
            acc *= 2.0f / 128.0f;
        }
        g_Mout[idx] = acc;
    }
}

// ---------------- GEMM1: X@W1, 256x128 tile, 512 thr, pipelined ----------------
// stage: AHI 32K @0, ALO @32768, BHI 16K @65536, BLO @81920; stride 98304
#define G1_STG 98304
__device__ __forceinline__ void g1_load(uint32_t sst, int bm, int bn, int k0, int tid) {
    #pragma unroll
    for (int u = tid; u < 2048; u += 512) {
        int r = u >> 3, cb = (u & 7) * 16;
        uint32_t d = swz64(r, cb);
        cp16(sst + d,         (const char*)g_Xhi + ((size_t)(bm + r) * 128 + k0) * 2 + cb);
        cp16(sst + 32768 + d, (const char*)g_Xlo + ((size_t)(bm + r) * 128 + k0) * 2 + cb);
    }
    #pragma unroll
    for (int u = tid; u < 1024; u += 512) {
        int r = u >> 3, cb = (u & 7) * 16;
        uint32_t d = swz64(r, cb);
        cp16(sst + 65536 + d, (const char*)g_W1T_hi + ((size_t)(bn + r) * 128 + k0) * 2 + cb);
        cp16(sst + 81920 + d, (const char*)g_W1T_lo + ((size_t)(bn + r) * 128 + k0) * 2 + cb);
    }
}

__global__ void __launch_bounds__(512, 1) gemm1_tc() {
    extern __shared__ char smem[];
    uint32_t sb = smem_u32(smem);
    int tid = threadIdx.x;
    int lane = tid & 31, wid = tid >> 5;
    int wm = wid & 7, wn = wid >> 3;      // 8 x 2 warps over 256 x 128
    int bm = blockIdx.y * 256, bn = blockIdx.x * 128;

    g1_load(sb, bm, bn, 0, tid);  cp_commit();
    g1_load(sb + G1_STG, bm, bn, 64, tid);  cp_commit();

    float c[2][8][4];
    #pragma unroll
    for (int i = 0; i < 2; i++)
        #pragma unroll
        for (int j = 0; j < 8; j++)
            #pragma unroll
            for (int k = 0; k < 4; k++) c[i][j][k] = 0.f;

    cp_wait1();
    __syncthreads();
    mma_chunk64(sb, sb + 32768, sb + 65536, sb + 81920, lane, wm, wn, c);
    cp_wait0();
    __syncthreads();
    mma_chunk64(sb + G1_STG, sb + G1_STG + 32768, sb + G1_STG + 65536,
                sb + G1_STG + 81920, lane, wm, wn, c);

    // fused epilogue: (re,im) adjacent; index math hoisted per tn
    int g = lane >> 2, cp2 = (lane & 3) * 2;
    #pragma unroll
    for (int tn = 0; tn < 8; tn++) {
        int col = bn + wn * 64 + tn * 8 + cp2;   // even
        if (col >= N1_) continue;
        int region = col / 1040;
        int cc = col - region * 1040;
        int hd = cc / 130;
        int uu = cc - hd * 130;
        int f = uu >> 1;
        #pragma unroll
        for (int tm = 0; tm < 2; tm++)
            #pragma unroll
            for (int hf = 0; hf < 2; hf++) {
                size_t row = (size_t)bm + wm * 32 + tm * 16 + hf * 8 + g;
                float re = c[tm][tn][hf * 2], im = c[tm][tn][hf * 2 + 1];
                if (region == 0) {
                    g_aq[(row * 8 + hd) * 65 + f] = sqrtf(re * re + im * im);
                } else if (region == 1) {
                    g_ak[(row * 8 + hd) * 65 + f] = sqrtf(re * re + im * im);
                } else {
                    __nv_bfloat16 rh = __float2bfloat16(re), ih = __float2bfloat16(im);
                    __nv_bfloat16 rl = __float2bfloat16(re - __bfloat162float(rh));
                    __nv_bfloat16 il = __float2bfloat16(im - __bfloat162float(ih));
                    size_t off = (row * NKP_ + cc) * 2;
                    *(uint32_t*)((char*)g_Vhi + off) = pack_bf(rh, ih);
                    *(uint32_t*)((char*)g_Vlo + off) = pack_bf(rl, il);
                }
            }
    }
}

// ---------------- att partial (EQ_ e-chunks of 256) ----------------
__global__ void __launch_bounds__(256) att_partial_kernel() {
    __shared__ float sm[8320];
    float* aqs = sm;
    float* aks = sm + 4160;
    int bh = blockIdx.y;
    int b = bh >> 3, h = bh & 7;
    int chunk = blockIdx.x;
    int tid = threadIdx.x;
    int tx = tid & 15, ty = tid >> 4;
    int xs[5], ys[5];
    #pragma unroll
    for (int i = 0; i < 5; i++) {
        int x = tx + 16 * i; xs[i] = (x < 65) ? x : 0;
        int y = ty + 16 * i; ys[i] = (y < 65) ? y : 0;
    }
    float acc[5][5];
    #pragma unroll
    for (int i = 0; i < 5; i++)
        #pragma unroll
        for (int j = 0; j < 5; j++) acc[i][j] = 0.f;

    int ebase = chunk * (2048 / EQ_);
    for (int e0 = ebase; e0 < ebase + 2048 / EQ_; e0 += 64) {
        for (int idx = tid; idx < 4160; idx += 256) {
            int r = idx / 65, f = idx - r * 65;
            size_t gidx = ((size_t)((b * 2048 + e0 + r) * 8 + h)) * 65 + f;
            aqs[idx] = g_aq[gidx];
            aks[idx] = g_ak[gidx];
        }
        __syncthreads();
        #pragma unroll 4
        for (int e = 0; e < 64; e++) {
            float av[5], bv[5];
            #pragma unroll
            for (int i = 0; i < 5; i++) av[i] = aqs[e * 65 + xs[i]];
            #pragma unroll
            for (int j = 0; j < 5; j++) bv[j] = aks[e * 65 + ys[j]];
            #pragma unroll
            for (int i = 0; i < 5; i++)
                #pragma unroll
                for (int j = 0; j < 5; j++) acc[i][j] += av[i] * bv[j];
        }
        __syncthreads();
    }
    float* dst = g_attp + (size_t)(bh * EQ_ + chunk) * 4225;
    #pragma unroll
    for (int i = 0; i < 5; i++) {
        int x = tx + 16 * i;
        if (x < 65)
            #pragma unroll
            for (int j = 0; j < 5; j++) {
                int y = ty + 16 * j;
                if (y < 65) dst[x * 65 + y] = acc[i][j];
            }
    }
}

// ---------------- softmax ----------------
__global__ void __launch_bounds__(256) att_softmax_kernel() {
    __shared__ float sm[4225];
    int bh = blockIdx.x;
    int tid = threadIdx.x;
    const float* p0 = g_attp + (size_t)(bh * EQ_) * 4225;
    for (int idx = tid; idx < 4225; idx += 256) {
        float s = 0.f;
        #pragma unroll
        for (int q = 0; q < EQ_; q++) s += p0[q * 4225 + idx];
        sm[idx] = s;
    }
    __syncthreads();
    int warp = tid >> 5, lane = tid & 31;
    for (int x = warp; x < 65; x += 8) {
        float m = -3.4e38f;
        for (int y = lane; y < 65; y += 32) m = fmaxf(m, sm[x * 65 + y]);
        #pragma unroll
        for (int o = 16; o; o >>= 1) m = fmaxf(m, __shfl_xor_sync(0xffffffffu, m, o));
        float s = 0.f;
        for (int y = lane; y < 65; y += 32) {
            float v = expf(sm[x * 65 + y] - m);
            sm[x * 65 + y] = v;
            s += v;
        }
        #pragma unroll
        for (int o = 16; o; o >>= 1) s += __shfl_xor_sync(0xffffffffu, s, o);
        float inv = 1.0f / s;
        for (int y = lane; y < 65; y += 32)
            g_att[(size_t)bh * 4225 + x * 65 + y] = sm[x * 65 + y] * inv;
    }
}

// ---------------- build C_b ----------------
__global__ void __launch_bounds__(256) build_c_kernel() {
    extern __shared__ float csm[];
    float* att_s = csm;
    float* mout_s = csm + 4225;
    int blk = blockIdx.x;                    // b*16 + h*2 + p
    int b = blk >> 4;
    int hp = blk & 15;
    int hd = hp >> 1, p = hp & 1;
    int tid = threadIdx.x;
    int bh = b * 8 + hd;
    for (int idx = tid; idx < 4225; idx += 256)
        att_s[idx] = g_att[(size_t)bh * 4225 + idx];
    for (int idx = tid; idx < 8320; idx += 256)
        mout_s[idx] = g_Mout[(size_t)hp * 8320 + idx];
    __syncthreads();
    for (int idx = tid; idx < 8320; idx += 256) {
        int o = idx / 65, y = idx - o * 65;
        float acc = 0.f;
        #pragma unroll 5
        for (int x = 0; x < 65; x++)
            acc += att_s[x * 65 + y] * mout_s[x * 128 + o];
        int k = hd * 130 + 2 * y + p;
        __nv_bfloat16 hi = __float2bfloat16(acc);
        size_t off = ((size_t)b * 128 + o) * NKP_ + k;
        g_CThi[off] = hi;
        g_CTlo[off] = __float2bfloat16(acc - __bfloat162float(hi));
    }
}

// ---------------- GEMM2: out = V_b @ CT_b^T + bias (256-tile, pipelined) ----------------
#define G2_STG 98304
__device__ __forceinline__ void g2_load(uint32_t sst, int bm,
                                        const __nv_bfloat16* CThi,
                                        const __nv_bfloat16* CTlo,
                                        int k0, int tid) {
    #pragma unroll
    for (int u = tid; u < 2048; u += 512) {
        int r = u >> 3, cb = (u & 7) * 16;
        uint32_t d = swz64(r, cb);
        cp16(sst + d,         (const char*)g_Vhi + ((size_t)(bm + r) * NKP_ + k0) * 2 + cb);
        cp16(sst + 32768 + d, (const char*)g_Vlo + ((size_t)(bm + r) * NKP_ + k0) * 2 + cb);
    }
    #pragma unroll
    for (int u = tid; u < 1024; u += 512) {
        int r = u >> 3, cb = (u & 7) * 16;
        uint32_t d = swz64(r, cb);
        cp16(sst + 65536 + d, (const char*)CThi + ((size_t)r * NKP_ + k0) * 2 + cb);
        cp16(sst + 81920 + d, (const char*)CTlo + ((size_t)r * NKP_ + k0) * 2 + cb);
    }
}

__global__ void __launch_bounds__(512, 1) gemm2_tc(float* __restrict__ out,
                                                   const float* __restrict__ bias) {
    extern __shared__ char smem[];
    uint32_t sb = smem_u32(smem);
    int tid = threadIdx.x;
    int lane = tid & 31, wid = tid >> 5;
    int wm = wid & 7, wn = wid >> 3;     // 8 x 2 warps over 256 x 128
    int bm = blockIdx.x * 256;
    int b = bm >> 11;
    const __nv_bfloat16* CThi = g_CThi + (size_t)b * 128 * NKP_;
    const __nv_bfloat16* CTlo = g_CTlo + (size_t)b * 128 * NKP_;

    float c[2][8][4];
    #pragma unroll
    for (int i = 0; i < 2; i++)
        #pragma unroll
        for (int j = 0; j < 8; j++)
            #pragma unroll
            for (int k = 0; k < 4; k++) c[i][j][k] = 0.f;

    g2_load(sb, bm, CThi, CTlo, 0, tid);  cp_commit();
    g2_load(sb + G2_STG, bm, CThi, CTlo, 64, tid);  cp_commit();

    for (int kc = 0; kc < 18; kc++) {
        if (kc < 17) cp_wait1(); else cp_wait0();
        __syncthreads();
        uint32_t sst = sb + (kc & 1) * G2_STG;
        mma_chunk64(sst, sst + 32768, sst + 65536, sst + 81920, lane, wm, wn, c);
        __syncthreads();
        if (kc + 2 < 18) {
            g2_load(sst, bm, CThi, CTlo, (kc + 2) * 64, tid);
            cp_commit();
        }
    }

    int g = lane >> 2, cp2 = (lane & 3) * 2;
    #pragma unroll
    for (int tm = 0; tm < 2; tm++)
        #pragma unroll
        for (int hf = 0; hf < 2; hf++) {
            size_t row = (size_t)bm + wm * 32 + tm * 16 + hf * 8 + g;
            float* dst = out + row * 128;
            #pragma unroll
            for (int tn = 0; tn < 8; tn++) {
                int col = wn * 64 + tn * 8 + cp2;
                float2 bv = *(const float2*)(bias + col);
                *(float2*)(dst + col) = make_float2(c[tm][tn][hf * 2] + bv.x,
                                                    c[tm][tn][hf * 2 + 1] + bv.y);
            }
        }
}

// ---------------- launch ----------------
extern "C" void kernel_launch(void* const* d_in, const int* in_sizes, int n_in,
                              void* d_out, int out_size) {
    const float* x     = (const float*)d_in[0];
    const float* w_qkv = (const float*)d_in[1];
    const float* w_out = (const float*)d_in[2];
    const float* b_out = (const float*)d_in[3];
    float* out = (float*)d_out;

    cudaFuncSetAttribute(gemm1_tc, cudaFuncAttributeMaxDynamicSharedMemorySize, 2 * G1_STG);
    cudaFuncSetAttribute(gemm2_tc, cudaFuncAttributeMaxDynamicSharedMemorySize, 2 * G2_STG);
    cudaFuncSetAttribute(build_c_kernel, cudaFuncAttributeMaxDynamicSharedMemorySize,
                         (4225 + 8320) * 4);

    split_x_kernel<<<ROWS_ * D_ / 4 / 256, 256>>>(x);
    build_w1_kernel<<<480, 256>>>(w_qkv);
    build_mout_kernel<<<130, 256>>>(w_out);
    gemm1_tc<<<dim3(N1P_ / 128, ROWS_ / 256), 512, 2 * G1_STG>>>();
    att_partial_kernel<<<dim3(EQ_, B_ * H_), 256>>>();
    att_softmax_kernel<<<B_ * H_, 256>>>();
    build_c_kernel<<<B_ * H_ * 2, 256, (4225 + 8320) * 4>>>();
    gemm2_tc<<<ROWS_ / 256, 512, 2 * G2_STG>>>(out, b_out);
}